// round 11
// baseline (speedup 1.0000x reference)
#include <cuda_runtime.h>
#include <cuda_bf16.h>
#include <math.h>

// ---------------- problem constants ----------------
#define SQ      1024        // S (new tokens)
#define DMODEL  2048
#define NH      16
#define NKV     8
#define HD      128
#define FFD     8192
#define NL      4
#define HISTLEN 1024
#define TTOT    2048        // HIST + S
#define VOC     32000
#define KVDT    (NKV*HD*TTOT)   // elements of one k (or v) cache output: 2097152

// ---------------- scratch (device globals; allocation-free) ----------------
__device__ float g_h[SQ*DMODEL];
__device__ float g_hn[SQ*DMODEL];
__device__ float g_q[SQ*NH*HD];
__device__ float g_kt[SQ*NKV*HD];
__device__ float g_vt[SQ*NKV*HD];
__device__ float g_ctx[SQ*NH*HD];
__device__ float g_gate[SQ*FFD];
__device__ float g_up[SQ*FFD];
__device__ float g_last[DMODEL];
__device__ float g_att[(size_t)NH*SQ*HISTLEN];   // 64MB attention scores/probs
__device__ int   g_idmode;   // 0=i32 1=i64 2=f32
__device__ int   g_eqmode;   // 0=u8  1=f32 2=i32

// ---------------- dtype sniffing (data-dependent => deterministic) ----------------
__global__ void sniff_kernel(const void* ids_raw, const void* eq_raw)
{
    if (threadIdx.x != 0 || blockIdx.x != 0) return;

    // ---- input_ids dtype ----
    const int* ii = (const int*)ids_raw;
    bool i64ok = true;
    for (int i = 0; i < 128; i++) {
        int lo = ii[2*i], hi = ii[2*i + 1];
        if (hi != 0 || lo < 0 || lo >= VOC) { i64ok = false; break; }
    }
    if (i64ok) { g_idmode = 1; }
    else {
        bool i32ok = true;
        for (int i = 0; i < 256; i++) {
            int v = ii[i];
            if (v < 0 || v >= VOC) { i32ok = false; break; }
        }
        if (i32ok) g_idmode = 0;
        else {
            const float* ff = (const float*)ids_raw;
            bool f32ok = true;
            for (int i = 0; i < 256; i++) {
                float v = ff[i];
                if (!(v >= 0.f && v < (float)VOC && v == rintf(v))) { f32ok = false; break; }
            }
            g_idmode = f32ok ? 2 : 0;
        }
    }

    // ---- embed_q dtype ----
    const float* ef = (const float*)eq_raw;
    bool ef32 = true;
    for (int i = 0; i < 256; i++) {
        float v = ef[i];
        if (!(v >= 0.f && v <= 255.f && v == rintf(v))) { ef32 = false; break; }
    }
    if (ef32) { g_eqmode = 1; }
    else {
        const int* ei = (const int*)eq_raw;
        bool ei32 = true;
        for (int i = 0; i < 256; i++) {
            int v = ei[i];
            if (v < 0 || v > 255) { ei32 = false; break; }
        }
        g_eqmode = ei32 ? 2 : 0;
    }
}

// ---------------- embedding dequant (dtype-agnostic) ----------------
__global__ void embed_kernel(const void* __restrict__ ids_raw,
                             const void* __restrict__ eq_raw,
                             const float* __restrict__ sc,
                             const float* __restrict__ zp,
                             float* __restrict__ h)
{
    int idx = blockIdx.x * blockDim.x + threadIdx.x;
    if (idx >= SQ*DMODEL) return;
    int s = idx >> 11;          // / 2048
    int c = idx & 2047;
    int idm = g_idmode;
    int id;
    if (idm == 0)      id = ((const int*)ids_raw)[s];
    else if (idm == 1) id = (int)((const long long*)ids_raw)[s];
    else               id = (int)((const float*)ids_raw)[s];
    size_t off = (size_t)id * DMODEL + c;
    int em = g_eqmode;
    float qv;
    if (em == 0)      qv = (float)((const unsigned char*)eq_raw)[off];
    else if (em == 1) qv = ((const float*)eq_raw)[off];
    else              qv = (float)((const int*)eq_raw)[off];
    h[idx] = qv * sc[id] + zp[id];
}

// ---------------- rmsnorm (one block per row) ----------------
__global__ void rmsnorm_kernel(const float* __restrict__ x, const float* __restrict__ w,
                               float* __restrict__ out, int dim)
{
    int row = blockIdx.x;
    const float* xr = x + (size_t)row * dim;
    float ss = 0.f;
    for (int i = threadIdx.x; i < dim; i += blockDim.x) {
        float v = xr[i]; ss += v * v;
    }
#pragma unroll
    for (int o = 16; o > 0; o >>= 1) ss += __shfl_xor_sync(0xffffffffu, ss, o);
    __shared__ float wsum[8];
    if ((threadIdx.x & 31) == 0) wsum[threadIdx.x >> 5] = ss;
    __syncthreads();
    float tot = 0.f;
    int nw = blockDim.x >> 5;
    for (int k = 0; k < nw; k++) tot += wsum[k];
    float inv = rsqrtf(tot / (float)dim + 1e-6f);
    float* orow = out + (size_t)row * dim;
    for (int i = threadIdx.x; i < dim; i += blockDim.x)
        orow[i] = w[i] * xr[i] * inv;
}

// ---------------- generic strided/batched fp32 GEMM ----------------
// C[M,N] (+)= A[M,K] @ B[K,N], element strides lda/ldb/ldc.
// Per-z offsets: A += z*saz, B += (z>>zdivB)*sbz, C += z*scz  (zdivB handles GQA).
// BM=128 BN=64 BK=16, 256 threads, 8x4 microtile. Static smem only (12.8KB).
__global__ void __launch_bounds__(256) gemm2(
    const float* __restrict__ A, const float* __restrict__ B, float* __restrict__ C,
    int M, int N, int K, int lda, int ldb, int ldc,
    long long saz, long long sbz, long long scz, int zdivB, int beta)
{
    A += (long long)blockIdx.z * saz;
    B += (long long)(blockIdx.z >> zdivB) * sbz;
    C += (long long)blockIdx.z * scz;

    __shared__ float As[16 * 132];   // transposed A tile, padded
    __shared__ float Bs[16 * 68];    // B tile, padded
    int tid = threadIdx.x;
    int tx = tid & 15;
    int ty = tid >> 4;
    int n0 = blockIdx.x * 64;
    int m0 = blockIdx.y * 128;

    float acc[8][4];
#pragma unroll
    for (int i = 0; i < 8; i++)
#pragma unroll
        for (int j = 0; j < 4; j++) acc[i][j] = 0.f;

    for (int kk = 0; kk < K; kk += 16) {
#pragma unroll
        for (int i = 0; i < 2; i++) {
            int f = tid + i * 256;          // 0..511 float4 ids
            int m = f >> 2;                 // 0..127
            int kq = (f & 3) << 2;          // 0,4,8,12
            float4 v = *(const float4*)(A + (size_t)(m0 + m) * lda + kk + kq);
            As[(kq + 0) * 132 + m] = v.x;
            As[(kq + 1) * 132 + m] = v.y;
            As[(kq + 2) * 132 + m] = v.z;
            As[(kq + 3) * 132 + m] = v.w;
        }
        {
            int r = tid >> 4;               // 0..15
            int c = (tid & 15) << 2;        // 0..60
            *(float4*)(&Bs[r * 68 + c]) = *(const float4*)(B + (size_t)(kk + r) * ldb + n0 + c);
        }
        __syncthreads();
#pragma unroll
        for (int k2 = 0; k2 < 16; k2++) {
            float4 a0 = *(const float4*)(&As[k2 * 132 + ty * 8]);
            float4 a1 = *(const float4*)(&As[k2 * 132 + ty * 8 + 4]);
            float4 bv = *(const float4*)(&Bs[k2 * 68 + tx * 4]);
            float a[8] = {a0.x, a0.y, a0.z, a0.w, a1.x, a1.y, a1.z, a1.w};
            float b[4] = {bv.x, bv.y, bv.z, bv.w};
#pragma unroll
            for (int i = 0; i < 8; i++)
#pragma unroll
                for (int j = 0; j < 4; j++)
                    acc[i][j] += a[i] * b[j];
        }
        __syncthreads();
    }

#pragma unroll
    for (int i = 0; i < 8; i++) {
        float* cp = C + (size_t)(m0 + ty * 8 + i) * ldc + n0 + tx * 4;
        float4 v;
        if (beta) {
            float4 o = *(const float4*)cp;
            v.x = o.x + acc[i][0]; v.y = o.y + acc[i][1];
            v.z = o.z + acc[i][2]; v.w = o.w + acc[i][3];
        } else {
            v.x = acc[i][0]; v.y = acc[i][1]; v.z = acc[i][2]; v.w = acc[i][3];
        }
        *(float4*)cp = v;
    }
}

// ---------------- RoPE + q/k rmsnorm ----------------
// grid (S, NH+NKV), 128 threads. q in-place; new k into cache layout (d-major).
__global__ void rope_norm_kernel(float* __restrict__ q, const float* __restrict__ kt,
                                 const float* __restrict__ qn_w, const float* __restrict__ kn_w,
                                 float* __restrict__ kout)
{
    int s = blockIdx.x;
    int head = blockIdx.y;
    int d = threadIdx.x;
    bool isq = (head < NH);
    const float* src = isq ? (q  + (size_t)s * NH * HD + head * HD)
                           : (kt + (size_t)s * NKV * HD + (head - NH) * HD);
    float x  = src[d];
    float xp = src[(d < 64) ? d + 64 : d - 64];
    int i2 = d & 63;
    // inv_freq correctly rounded to f32; angle in f32 (replicates pos*inv_freq);
    // trig in double so fast-math can't substitute inaccurate single-precision
    // intrinsics; then fp16 rounding like the reference tables.
    float invf = (float)exp(-log(10000.0) * ((double)(2 * i2) / 128.0));
    float ang = (float)(HISTLEN + s) * invf;
    float c  = __half2float(__float2half((float)cos((double)ang)));
    float sn = __half2float(__float2half((float)sin((double)ang)));
    float r = (d < 64) ? (x * c - xp * sn) : (x * c + xp * sn);

    float ss = r * r;
#pragma unroll
    for (int o = 16; o > 0; o >>= 1) ss += __shfl_xor_sync(0xffffffffu, ss, o);
    __shared__ float wsum[4];
    if ((d & 31) == 0) wsum[d >> 5] = ss;
    __syncthreads();
    float tot = wsum[0] + wsum[1] + wsum[2] + wsum[3];
    float inv = rsqrtf(tot * (1.0f / 128.0f) + 1e-6f);
    float w = isq ? qn_w[d] : kn_w[d];
    float out = w * r * inv;
    if (isq) {
        q[(size_t)s * NH * HD + head * HD + d] = out;
    } else {
        int kvh = head - NH;
        kout[(size_t)kvh * HD * TTOT + (size_t)d * TTOT + HISTLEN + s] = out;
    }
}

// ---------------- masked softmax over scores row (h, s, 0..HIST) ----------------
// mask: only t <= s contribute (t <= s < HIST; new-token keys carry -128 bias
// => weights <= e^-116 relative: exactly negligible in fp32).
__global__ void att_softmax_kernel(float* __restrict__ P)
{
    int s = blockIdx.x;
    int h = blockIdx.y;
    float* row = P + ((size_t)h * SQ + s) * HISTLEN;
    int n = s + 1;
    int tid = threadIdx.x;
    __shared__ float red[8];

    float mx = -1e30f;
    for (int t = tid; t < n; t += 256) mx = fmaxf(mx, row[t]);
#pragma unroll
    for (int o = 16; o > 0; o >>= 1) mx = fmaxf(mx, __shfl_xor_sync(0xffffffffu, mx, o));
    if ((tid & 31) == 0) red[tid >> 5] = mx;
    __syncthreads();
    mx = fmaxf(fmaxf(fmaxf(red[0], red[1]), fmaxf(red[2], red[3])),
               fmaxf(fmaxf(red[4], red[5]), fmaxf(red[6], red[7])));

    float sum = 0.f;
    for (int t = tid; t < n; t += 256) {
        float p = __expf(row[t] - mx);
        row[t] = p;
        sum += p;
    }
#pragma unroll
    for (int o = 16; o > 0; o >>= 1) sum += __shfl_xor_sync(0xffffffffu, sum, o);
    __syncthreads();                 // everyone done reading red for max
    if ((tid & 31) == 0) red[tid >> 5] = sum;
    __syncthreads();
    sum = red[0] + red[1] + red[2] + red[3] + red[4] + red[5] + red[6] + red[7];
    float inv = 1.f / sum;
    for (int t = tid; t < HISTLEN; t += 256)
        row[t] = (t < n) ? row[t] * inv : 0.f;
}

// ---------------- cache assembly ----------------
__global__ void copy_khist_kernel(const float* __restrict__ src, float* __restrict__ dst)
{
    int idx = blockIdx.x * blockDim.x + threadIdx.x;
    if (idx >= NKV * HD * HISTLEN) return;
    int t = idx & (HISTLEN - 1);
    int row = idx >> 10;                           // kv*D + d
    dst[(size_t)row * TTOT + t] = src[idx];
}

__global__ void copy_vhist_kernel(const float* __restrict__ src, float* __restrict__ dst)
{
    int idx = blockIdx.x * blockDim.x + threadIdx.x;
    if (idx >= NKV * HISTLEN * HD) return;
    int within = idx & (HISTLEN * HD - 1);
    int kv = idx >> 17;
    dst[(size_t)kv * TTOT * HD + within] = src[idx];
}

__global__ void vscatter_kernel(const float* __restrict__ vt, float* __restrict__ dst)
{
    int idx = blockIdx.x * blockDim.x + threadIdx.x;   // S*KV*D
    if (idx >= SQ * NKV * HD) return;
    int d = idx & 127;
    int kv = (idx >> 7) & 7;
    int s = idx >> 10;
    dst[(size_t)kv * TTOT * HD + (size_t)(HISTLEN + s) * HD + d] = vt[idx];
}

// ---------------- silu(gate)*up ----------------
__global__ void silu_mul_kernel(const float* __restrict__ g, const float* __restrict__ u,
                                float* __restrict__ o, int n)
{
    int i = blockIdx.x * blockDim.x + threadIdx.x;
    if (i < n) {
        float x = g[i];
        o[i] = (x / (1.f + expf(-x))) * u[i];
    }
}

// ---------------- lm head GEMV: logits = x @ W (DM, V) ----------------
__global__ void lmhead_kernel(const float* __restrict__ x, const float* __restrict__ W,
                              float* __restrict__ out)
{
    __shared__ float xs[256];
    int v = blockIdx.x * 256 + threadIdx.x;
    float acc = 0.f;
    for (int k0 = 0; k0 < DMODEL; k0 += 256) {
        xs[threadIdx.x] = x[k0 + threadIdx.x];
        __syncthreads();
#pragma unroll 16
        for (int k = 0; k < 256; k++)
            acc += xs[k] * W[(size_t)(k0 + k) * VOC + v];
        __syncthreads();
    }
    if (v < VOC) out[v] = acc;
}

// ---------------- host launcher ----------------
extern "C" void kernel_launch(void* const* d_in, const int* in_sizes, int n_in,
                              void* d_out, int out_size)
{
    // Input-order detection from in_sizes (host data => deterministic):
    // dict order has in_sizes[0] == 1024 (input_ids); alphabetical order starts
    // with down_w (67108864). Remap accordingly.
    int IX[19];
    for (int i = 0; i < 19; i++) IX[i] = i;
    if (n_in >= 19 && in_sizes[0] != 1024) {
        // alphabetical: down_w, embed_q, embed_scale, embed_zp, gate_w, input_ids,
        // k_cache, k_w, kn_w, ln1_w, ln2_w, lm_head_w, norm_w, o_w, q_w, qn_w,
        // up_w, v_cache, v_w
        const int amap[19] = {5, 6, 17, 1, 2, 3, 9, 14, 7, 18, 15, 8, 13, 10, 4, 16, 0, 12, 11};
        for (int i = 0; i < 19; i++) IX[i] = amap[i];
    }

    const void*          input_ids   = d_in[IX[0]];
    const float*         k_cache     = (const float*)d_in[IX[1]];
    const float*         v_cache     = (const float*)d_in[IX[2]];
    const void*          embed_q     = d_in[IX[3]];
    const float*         embed_scale = (const float*)d_in[IX[4]];
    const float*         embed_zp    = (const float*)d_in[IX[5]];
    const float*         ln1_w       = (const float*)d_in[IX[6]];
    const float*         q_w         = (const float*)d_in[IX[7]];
    const float*         k_w         = (const float*)d_in[IX[8]];
    const float*         v_w         = (const float*)d_in[IX[9]];
    const float*         qn_w        = (const float*)d_in[IX[10]];
    const float*         kn_w        = (const float*)d_in[IX[11]];
    const float*         o_w         = (const float*)d_in[IX[12]];
    const float*         ln2_w       = (const float*)d_in[IX[13]];
    const float*         gate_w      = (const float*)d_in[IX[14]];
    const float*         up_w        = (const float*)d_in[IX[15]];
    const float*         down_w      = (const float*)d_in[IX[16]];
    const float*         norm_w      = (const float*)d_in[IX[17]];
    const float*         lm_head_w   = (const float*)d_in[IX[18]];
    float* out = (float*)d_out;

    bool write_caches = (out_size >= (int)(VOC + 8u * KVDT));

    float *h_, *hn_, *q_, *kt_, *vt_, *ctx_, *gate_, *up_, *last_, *att_;
    cudaGetSymbolAddress((void**)&h_,    g_h);
    cudaGetSymbolAddress((void**)&hn_,   g_hn);
    cudaGetSymbolAddress((void**)&q_,    g_q);
    cudaGetSymbolAddress((void**)&kt_,   g_kt);
    cudaGetSymbolAddress((void**)&vt_,   g_vt);
    cudaGetSymbolAddress((void**)&ctx_,  g_ctx);
    cudaGetSymbolAddress((void**)&gate_, g_gate);
    cudaGetSymbolAddress((void**)&up_,   g_up);
    cudaGetSymbolAddress((void**)&last_, g_last);
    cudaGetSymbolAddress((void**)&att_,  g_att);

    // detect dtypes of input_ids / embed_q, then dequantize embedding
    sniff_kernel<<<1, 1>>>(input_ids, embed_q);
    embed_kernel<<<(SQ*DMODEL + 255) / 256, 256>>>(input_ids, embed_q, embed_scale, embed_zp, h_);

    for (int l = 0; l < NL; l++) {
        float* kout = out + VOC + (size_t)l * KVDT;
        float* vout = out + VOC + (size_t)(NL + l) * KVDT;
        // if the harness only compares logits, keep cache writes inside scratch
        if (!write_caches) { kout = att_; vout = att_ + KVDT; }  // att_ unused until scores
        const float* kcl = k_cache + (size_t)l * NKV * HD * HISTLEN;
        const float* vcl = v_cache + (size_t)l * NKV * HISTLEN * HD;

        if (write_caches) {
            copy_khist_kernel<<<(NKV*HD*HISTLEN + 255) / 256, 256>>>(kcl, kout);
            copy_vhist_kernel<<<(NKV*HISTLEN*HD + 255) / 256, 256>>>(vcl, vout);
        }

        rmsnorm_kernel<<<SQ, 256>>>(h_, ln1_w + (size_t)l * DMODEL, hn_, DMODEL);

        // QKV projections
        gemm2<<<dim3((NH*HD)/64,  SQ/128, 1), 256>>>(hn_, q_w + (size_t)l * DMODEL * NH * HD,  q_,
                    SQ, NH*HD,  DMODEL, DMODEL, NH*HD,  NH*HD,  0, 0, 0, 0, 0);
        gemm2<<<dim3((NKV*HD)/64, SQ/128, 1), 256>>>(hn_, k_w + (size_t)l * DMODEL * NKV * HD, kt_,
                    SQ, NKV*HD, DMODEL, DMODEL, NKV*HD, NKV*HD, 0, 0, 0, 0, 0);
        gemm2<<<dim3((NKV*HD)/64, SQ/128, 1), 256>>>(hn_, v_w + (size_t)l * DMODEL * NKV * HD, vt_,
                    SQ, NKV*HD, DMODEL, DMODEL, NKV*HD, NKV*HD, 0, 0, 0, 0, 0);

        rope_norm_kernel<<<dim3(SQ, NH + NKV), 128>>>(q_, kt_, qn_w + (size_t)l * HD, kn_w + (size_t)l * HD, kout);
        if (write_caches)
            vscatter_kernel<<<(SQ*NKV*HD + 255) / 256, 256>>>(vt_, vout);

        // scores[h] = Q_h (S x D, lda=2048) @ K_h (D x HIST, ldb=1024)  -> (S, HIST)
        gemm2<<<dim3(HISTLEN/64, SQ/128, NH), 256>>>(q_, kcl, att_,
                    SQ, HISTLEN, HD, DMODEL, HISTLEN, HISTLEN,
                    /*saz=*/HD, /*sbz=*/(long long)HD*HISTLEN, /*scz=*/(long long)SQ*HISTLEN,
                    /*zdivB=*/1, 0);

        att_softmax_kernel<<<dim3(SQ, NH), 256>>>(att_);

        // ctx[h] = P_h (S x HIST, lda=1024) @ V_h (HIST x D, ldb=128) -> (S, D) at col h*128
        gemm2<<<dim3(HD/64, SQ/128, NH), 256>>>(att_, vcl, ctx_,
                    SQ, HD, HISTLEN, HISTLEN, HD, DMODEL,
                    /*saz=*/(long long)SQ*HISTLEN, /*sbz=*/(long long)HISTLEN*HD, /*scz=*/HD,
                    /*zdivB=*/1, 0);

        // O projection (residual add)
        gemm2<<<dim3(DMODEL/64, SQ/128, 1), 256>>>(ctx_, o_w + (size_t)l * NH * HD * DMODEL, h_,
                    SQ, DMODEL, NH*HD, NH*HD, DMODEL, DMODEL, 0, 0, 0, 0, 1);

        rmsnorm_kernel<<<SQ, 256>>>(h_, ln2_w + (size_t)l * DMODEL, hn_, DMODEL);

        gemm2<<<dim3(FFD/64, SQ/128, 1), 256>>>(hn_, gate_w + (size_t)l * DMODEL * FFD, gate_,
                    SQ, FFD, DMODEL, DMODEL, FFD, FFD, 0, 0, 0, 0, 0);
        gemm2<<<dim3(FFD/64, SQ/128, 1), 256>>>(hn_, up_w   + (size_t)l * DMODEL * FFD, up_,
                    SQ, FFD, DMODEL, DMODEL, FFD, FFD, 0, 0, 0, 0, 0);
        silu_mul_kernel<<<(SQ*FFD + 255) / 256, 256>>>(gate_, up_, gate_, SQ*FFD);
        gemm2<<<dim3(DMODEL/64, SQ/128, 1), 256>>>(gate_, down_w + (size_t)l * FFD * DMODEL, h_,
                    SQ, DMODEL, FFD, FFD, DMODEL, DMODEL, 0, 0, 0, 0, 1);
    }

    rmsnorm_kernel<<<1, 256>>>(h_ + (size_t)(SQ - 1) * DMODEL, norm_w, last_, DMODEL);
    lmhead_kernel<<<VOC / 256, 256>>>(last_, lm_head_w, out);
}

// round 12
// speedup vs baseline: 1.0407x; 1.0407x over previous
#include <cuda_runtime.h>
#include <cuda_bf16.h>
#include <math.h>
#include <stdint.h>

// ---------------- problem constants ----------------
#define SQ      1024        // S (new tokens)
#define DMODEL  2048
#define NH      16
#define NKV     8
#define HD      128
#define FFD     8192
#define NL      4
#define HISTLEN 1024
#define TTOT    2048        // HIST + S
#define VOC     32000
#define KVDT    (NKV*HD*TTOT)   // elements of one k (or v) cache output: 2097152

// ---------------- scratch (device globals; allocation-free) ----------------
__device__ float g_h[SQ*DMODEL];
__device__ float g_hn[SQ*DMODEL];
__device__ float g_q[SQ*NH*HD];
__device__ float g_kt[SQ*NKV*HD];
__device__ float g_vt[SQ*NKV*HD];
__device__ float g_ctx[SQ*NH*HD];
__device__ float g_gate[SQ*FFD];
__device__ float g_up[SQ*FFD];
__device__ float g_last[DMODEL];
__device__ float g_att[(size_t)NH*SQ*HISTLEN];   // 64MB attention scores/probs
__device__ int   g_idmode;   // 0=i32 1=i64 2=f32
__device__ int   g_eqmode;   // 0=u8  1=f32 2=i32

// ---------------- dtype sniffing (data-dependent => deterministic) ----------------
__global__ void sniff_kernel(const void* ids_raw, const void* eq_raw)
{
    if (threadIdx.x != 0 || blockIdx.x != 0) return;

    const int* ii = (const int*)ids_raw;
    bool i64ok = true;
    for (int i = 0; i < 128; i++) {
        int lo = ii[2*i], hi = ii[2*i + 1];
        if (hi != 0 || lo < 0 || lo >= VOC) { i64ok = false; break; }
    }
    if (i64ok) { g_idmode = 1; }
    else {
        bool i32ok = true;
        for (int i = 0; i < 256; i++) {
            int v = ii[i];
            if (v < 0 || v >= VOC) { i32ok = false; break; }
        }
        if (i32ok) g_idmode = 0;
        else {
            const float* ff = (const float*)ids_raw;
            bool f32ok = true;
            for (int i = 0; i < 256; i++) {
                float v = ff[i];
                if (!(v >= 0.f && v < (float)VOC && v == rintf(v))) { f32ok = false; break; }
            }
            g_idmode = f32ok ? 2 : 0;
        }
    }

    const float* ef = (const float*)eq_raw;
    bool ef32 = true;
    for (int i = 0; i < 256; i++) {
        float v = ef[i];
        if (!(v >= 0.f && v <= 255.f && v == rintf(v))) { ef32 = false; break; }
    }
    if (ef32) { g_eqmode = 1; }
    else {
        const int* ei = (const int*)eq_raw;
        bool ei32 = true;
        for (int i = 0; i < 256; i++) {
            int v = ei[i];
            if (v < 0 || v > 255) { ei32 = false; break; }
        }
        g_eqmode = ei32 ? 2 : 0;
    }
}

// ---------------- embedding dequant (dtype-agnostic) ----------------
__global__ void embed_kernel(const void* __restrict__ ids_raw,
                             const void* __restrict__ eq_raw,
                             const float* __restrict__ sc,
                             const float* __restrict__ zp,
                             float* __restrict__ h)
{
    int idx = blockIdx.x * blockDim.x + threadIdx.x;
    if (idx >= SQ*DMODEL) return;
    int s = idx >> 11;
    int c = idx & 2047;
    int idm = g_idmode;
    int id;
    if (idm == 0)      id = ((const int*)ids_raw)[s];
    else if (idm == 1) id = (int)((const long long*)ids_raw)[s];
    else               id = (int)((const float*)ids_raw)[s];
    size_t off = (size_t)id * DMODEL + c;
    int em = g_eqmode;
    float qv;
    if (em == 0)      qv = (float)((const unsigned char*)eq_raw)[off];
    else if (em == 1) qv = ((const float*)eq_raw)[off];
    else              qv = (float)((const int*)eq_raw)[off];
    h[idx] = qv * sc[id] + zp[id];
}

// ---------------- rmsnorm (one block per row) ----------------
__global__ void rmsnorm_kernel(const float* __restrict__ x, const float* __restrict__ w,
                               float* __restrict__ out, int dim)
{
    int row = blockIdx.x;
    const float* xr = x + (size_t)row * dim;
    float ss = 0.f;
    for (int i = threadIdx.x; i < dim; i += blockDim.x) {
        float v = xr[i]; ss += v * v;
    }
#pragma unroll
    for (int o = 16; o > 0; o >>= 1) ss += __shfl_xor_sync(0xffffffffu, ss, o);
    __shared__ float wsum[8];
    if ((threadIdx.x & 31) == 0) wsum[threadIdx.x >> 5] = ss;
    __syncthreads();
    float tot = 0.f;
    int nw = blockDim.x >> 5;
    for (int k = 0; k < nw; k++) tot += wsum[k];
    float inv = rsqrtf(tot / (float)dim + 1e-6f);
    float* orow = out + (size_t)row * dim;
    for (int i = threadIdx.x; i < dim; i += blockDim.x)
        orow[i] = w[i] * xr[i] * inv;
}

// ---------------- tf32 helpers ----------------
__device__ __forceinline__ uint32_t f2tf32(float x) {
    uint32_t r;
    asm("cvt.rna.tf32.f32 %0, %1;" : "=r"(r) : "f"(x));
    return r;
}
// split x into hi (tf32) + lo (tf32), both stored as fp32 bit patterns
__device__ __forceinline__ void tf32_split(float x, float& hi, float& lo) {
    uint32_t hb = f2tf32(x);
    hi = __uint_as_float(hb);
    lo = __uint_as_float(f2tf32(x - hi));
}

#define MMA_TF32(C0,C1,C2,C3, A0,A1,A2,A3, B0,B1) \
    asm volatile("mma.sync.aligned.m16n8k8.row.col.f32.tf32.tf32.f32 " \
        "{%0,%1,%2,%3}, {%4,%5,%6,%7}, {%8,%9}, {%0,%1,%2,%3};" \
        : "+f"(C0), "+f"(C1), "+f"(C2), "+f"(C3) \
        : "r"(A0), "r"(A1), "r"(A2), "r"(A3), "r"(B0), "r"(B1))

// ---------------- tensor-core strided/batched GEMM (3xTF32, fp32-accurate) ----
// C[M,N] (+)= A[M,K] @ B[K,N]; strides lda/ldb/ldc; per-z offsets as before.
// BM=128 BN=64 BK=16, 256 threads (8 warps, 4x2), warp tile 32x32.
#define APAD 20
#define BPAD 36
__global__ void __launch_bounds__(256) gemm_tc(
    const float* __restrict__ A, const float* __restrict__ B, float* __restrict__ C,
    int M, int N, int K, int lda, int ldb, int ldc,
    long long saz, long long sbz, long long scz, int zdivB, int beta)
{
    A += (long long)blockIdx.z * saz;
    B += (long long)(blockIdx.z >> zdivB) * sbz;
    C += (long long)blockIdx.z * scz;

    __shared__ float Ah[128 * APAD];   // [m][k] hi
    __shared__ float Al[128 * APAD];   // [m][k] lo
    __shared__ float Bh[64 * BPAD];    // [n][k] hi
    __shared__ float Bl[64 * BPAD];    // [n][k] lo

    int tid  = threadIdx.x;
    int lane = tid & 31;
    int warp = tid >> 5;
    int wm = warp & 3;          // 0..3  -> m slab of 32
    int wn = warp >> 2;         // 0..1  -> n slab of 32
    int g = lane >> 2;          // 0..7
    int t = lane & 3;           // 0..3
    int m0 = blockIdx.y * 128;
    int n0 = blockIdx.x * 64;

    float acc[2][4][4];
#pragma unroll
    for (int i = 0; i < 2; i++)
#pragma unroll
        for (int j = 0; j < 4; j++)
#pragma unroll
            for (int k = 0; k < 4; k++) acc[i][j][k] = 0.f;

    for (int kk = 0; kk < K; kk += 16) {
        // ---- A tile 128x16 -> smem [m][k] (hi/lo), STS.128 ----
#pragma unroll
        for (int i = 0; i < 2; i++) {
            int f = tid + i * 256;          // float4 id 0..511
            int m = f >> 2;
            int kq = (f & 3) << 2;
            float4 v = *(const float4*)(A + (size_t)(m0 + m) * lda + kk + kq);
            float4 h4, l4;
            tf32_split(v.x, h4.x, l4.x);
            tf32_split(v.y, h4.y, l4.y);
            tf32_split(v.z, h4.z, l4.z);
            tf32_split(v.w, h4.w, l4.w);
            *(float4*)(&Ah[m * APAD + kq]) = h4;
            *(float4*)(&Al[m * APAD + kq]) = l4;
        }
        // ---- B tile 16x64 -> smem [n][k] transposed (hi/lo) ----
        {
            int r = tid & 15;               // k row
            int c = (tid >> 4) << 2;        // n col base
            float4 v = *(const float4*)(B + (size_t)(kk + r) * ldb + n0 + c);
            float h, l;
            tf32_split(v.x, h, l); Bh[(c + 0) * BPAD + r] = h; Bl[(c + 0) * BPAD + r] = l;
            tf32_split(v.y, h, l); Bh[(c + 1) * BPAD + r] = h; Bl[(c + 1) * BPAD + r] = l;
            tf32_split(v.z, h, l); Bh[(c + 2) * BPAD + r] = h; Bl[(c + 2) * BPAD + r] = l;
            tf32_split(v.w, h, l); Bh[(c + 3) * BPAD + r] = h; Bl[(c + 3) * BPAD + r] = l;
        }
        __syncthreads();

#pragma unroll
        for (int ks = 0; ks < 16; ks += 8) {
            uint32_t ah[2][4], al[2][4];
#pragma unroll
            for (int mt = 0; mt < 2; mt++) {
                int rb = (wm * 32 + mt * 16) * APAD + ks;
                ah[mt][0] = __float_as_uint(Ah[rb + g * APAD + t]);
                ah[mt][1] = __float_as_uint(Ah[rb + (g + 8) * APAD + t]);
                ah[mt][2] = __float_as_uint(Ah[rb + g * APAD + t + 4]);
                ah[mt][3] = __float_as_uint(Ah[rb + (g + 8) * APAD + t + 4]);
                al[mt][0] = __float_as_uint(Al[rb + g * APAD + t]);
                al[mt][1] = __float_as_uint(Al[rb + (g + 8) * APAD + t]);
                al[mt][2] = __float_as_uint(Al[rb + g * APAD + t + 4]);
                al[mt][3] = __float_as_uint(Al[rb + (g + 8) * APAD + t + 4]);
            }
#pragma unroll
            for (int nt = 0; nt < 4; nt++) {
                int nb = (wn * 32 + nt * 8 + g) * BPAD + ks;
                uint32_t bh0 = __float_as_uint(Bh[nb + t]);
                uint32_t bh1 = __float_as_uint(Bh[nb + t + 4]);
                uint32_t bl0 = __float_as_uint(Bl[nb + t]);
                uint32_t bl1 = __float_as_uint(Bl[nb + t + 4]);
#pragma unroll
                for (int mt = 0; mt < 2; mt++) {
                    float* c4 = acc[mt][nt];
                    MMA_TF32(c4[0], c4[1], c4[2], c4[3],
                             ah[mt][0], ah[mt][1], ah[mt][2], ah[mt][3], bh0, bh1);
                    MMA_TF32(c4[0], c4[1], c4[2], c4[3],
                             ah[mt][0], ah[mt][1], ah[mt][2], ah[mt][3], bl0, bl1);
                    MMA_TF32(c4[0], c4[1], c4[2], c4[3],
                             al[mt][0], al[mt][1], al[mt][2], al[mt][3], bh0, bh1);
                }
            }
        }
        __syncthreads();
    }

    // ---- epilogue ----
#pragma unroll
    for (int mt = 0; mt < 2; mt++) {
        int r0 = m0 + wm * 32 + mt * 16 + g;
#pragma unroll
        for (int nt = 0; nt < 4; nt++) {
            int cb = n0 + wn * 32 + nt * 8 + 2 * t;
            float* p0 = C + (size_t)r0 * ldc + cb;
            float* p1 = C + (size_t)(r0 + 8) * ldc + cb;
            float* c4 = acc[mt][nt];
            if (beta) {
                float2 o0 = *(float2*)p0, o1 = *(float2*)p1;
                o0.x += c4[0]; o0.y += c4[1];
                o1.x += c4[2]; o1.y += c4[3];
                *(float2*)p0 = o0; *(float2*)p1 = o1;
            } else {
                *(float2*)p0 = make_float2(c4[0], c4[1]);
                *(float2*)p1 = make_float2(c4[2], c4[3]);
            }
        }
    }
}

// ---------------- RoPE + q/k rmsnorm ----------------
__global__ void rope_norm_kernel(float* __restrict__ q, const float* __restrict__ kt,
                                 const float* __restrict__ qn_w, const float* __restrict__ kn_w,
                                 float* __restrict__ kout)
{
    int s = blockIdx.x;
    int head = blockIdx.y;
    int d = threadIdx.x;
    bool isq = (head < NH);
    const float* src = isq ? (q  + (size_t)s * NH * HD + head * HD)
                           : (kt + (size_t)s * NKV * HD + (head - NH) * HD);
    float x  = src[d];
    float xp = src[(d < 64) ? d + 64 : d - 64];
    int i2 = d & 63;
    float invf = (float)exp(-log(10000.0) * ((double)(2 * i2) / 128.0));
    float ang = (float)(HISTLEN + s) * invf;
    float c  = __half2float(__float2half((float)cos((double)ang)));
    float sn = __half2float(__float2half((float)sin((double)ang)));
    float r = (d < 64) ? (x * c - xp * sn) : (x * c + xp * sn);

    float ss = r * r;
#pragma unroll
    for (int o = 16; o > 0; o >>= 1) ss += __shfl_xor_sync(0xffffffffu, ss, o);
    __shared__ float wsum[4];
    if ((d & 31) == 0) wsum[d >> 5] = ss;
    __syncthreads();
    float tot = wsum[0] + wsum[1] + wsum[2] + wsum[3];
    float inv = rsqrtf(tot * (1.0f / 128.0f) + 1e-6f);
    float w = isq ? qn_w[d] : kn_w[d];
    float out = w * r * inv;
    if (isq) {
        q[(size_t)s * NH * HD + head * HD + d] = out;
    } else {
        int kvh = head - NH;
        kout[(size_t)kvh * HD * TTOT + (size_t)d * TTOT + HISTLEN + s] = out;
    }
}

// ---------------- masked softmax over scores row ----------------
__global__ void att_softmax_kernel(float* __restrict__ P)
{
    int s = blockIdx.x;
    int h = blockIdx.y;
    float* row = P + ((size_t)h * SQ + s) * HISTLEN;
    int n = s + 1;
    int tid = threadIdx.x;
    __shared__ float red[8];

    float mx = -1e30f;
    for (int t = tid; t < n; t += 256) mx = fmaxf(mx, row[t]);
#pragma unroll
    for (int o = 16; o > 0; o >>= 1) mx = fmaxf(mx, __shfl_xor_sync(0xffffffffu, mx, o));
    if ((tid & 31) == 0) red[tid >> 5] = mx;
    __syncthreads();
    mx = fmaxf(fmaxf(fmaxf(red[0], red[1]), fmaxf(red[2], red[3])),
               fmaxf(fmaxf(red[4], red[5]), fmaxf(red[6], red[7])));

    float sum = 0.f;
    for (int t = tid; t < n; t += 256) {
        float p = __expf(row[t] - mx);
        row[t] = p;
        sum += p;
    }
#pragma unroll
    for (int o = 16; o > 0; o >>= 1) sum += __shfl_xor_sync(0xffffffffu, sum, o);
    __syncthreads();
    if ((tid & 31) == 0) red[tid >> 5] = sum;
    __syncthreads();
    sum = red[0] + red[1] + red[2] + red[3] + red[4] + red[5] + red[6] + red[7];
    float inv = 1.f / sum;
    for (int t = tid; t < HISTLEN; t += 256)
        row[t] = (t < n) ? row[t] * inv : 0.f;
}

// ---------------- cache assembly ----------------
__global__ void copy_khist_kernel(const float* __restrict__ src, float* __restrict__ dst)
{
    int idx = blockIdx.x * blockDim.x + threadIdx.x;
    if (idx >= NKV * HD * HISTLEN) return;
    int t = idx & (HISTLEN - 1);
    int row = idx >> 10;
    dst[(size_t)row * TTOT + t] = src[idx];
}

__global__ void copy_vhist_kernel(const float* __restrict__ src, float* __restrict__ dst)
{
    int idx = blockIdx.x * blockDim.x + threadIdx.x;
    if (idx >= NKV * HISTLEN * HD) return;
    int within = idx & (HISTLEN * HD - 1);
    int kv = idx >> 17;
    dst[(size_t)kv * TTOT * HD + within] = src[idx];
}

__global__ void vscatter_kernel(const float* __restrict__ vt, float* __restrict__ dst)
{
    int idx = blockIdx.x * blockDim.x + threadIdx.x;
    if (idx >= SQ * NKV * HD) return;
    int d = idx & 127;
    int kv = (idx >> 7) & 7;
    int s = idx >> 10;
    dst[(size_t)kv * TTOT * HD + (size_t)(HISTLEN + s) * HD + d] = vt[idx];
}

// ---------------- silu(gate)*up ----------------
__global__ void silu_mul_kernel(const float* __restrict__ g, const float* __restrict__ u,
                                float* __restrict__ o, int n)
{
    int i = blockIdx.x * blockDim.x + threadIdx.x;
    if (i < n) {
        float x = g[i];
        o[i] = (x / (1.f + expf(-x))) * u[i];
    }
}

// ---------------- lm head GEMV ----------------
__global__ void lmhead_kernel(const float* __restrict__ x, const float* __restrict__ W,
                              float* __restrict__ out)
{
    __shared__ float xs[256];
    int v = blockIdx.x * 256 + threadIdx.x;
    float acc = 0.f;
    for (int k0 = 0; k0 < DMODEL; k0 += 256) {
        xs[threadIdx.x] = x[k0 + threadIdx.x];
        __syncthreads();
#pragma unroll 16
        for (int k = 0; k < 256; k++)
            acc += xs[k] * W[(size_t)(k0 + k) * VOC + v];
        __syncthreads();
    }
    if (v < VOC) out[v] = acc;
}

// ---------------- host launcher ----------------
extern "C" void kernel_launch(void* const* d_in, const int* in_sizes, int n_in,
                              void* d_out, int out_size)
{
    int IX[19];
    for (int i = 0; i < 19; i++) IX[i] = i;
    if (n_in >= 19 && in_sizes[0] != 1024) {
        const int amap[19] = {5, 6, 17, 1, 2, 3, 9, 14, 7, 18, 15, 8, 13, 10, 4, 16, 0, 12, 11};
        for (int i = 0; i < 19; i++) IX[i] = amap[i];
    }

    const void*          input_ids   = d_in[IX[0]];
    const float*         k_cache     = (const float*)d_in[IX[1]];
    const float*         v_cache     = (const float*)d_in[IX[2]];
    const void*          embed_q     = d_in[IX[3]];
    const float*         embed_scale = (const float*)d_in[IX[4]];
    const float*         embed_zp    = (const float*)d_in[IX[5]];
    const float*         ln1_w       = (const float*)d_in[IX[6]];
    const float*         q_w         = (const float*)d_in[IX[7]];
    const float*         k_w         = (const float*)d_in[IX[8]];
    const float*         v_w         = (const float*)d_in[IX[9]];
    const float*         qn_w        = (const float*)d_in[IX[10]];
    const float*         kn_w        = (const float*)d_in[IX[11]];
    const float*         o_w         = (const float*)d_in[IX[12]];
    const float*         ln2_w       = (const float*)d_in[IX[13]];
    const float*         gate_w      = (const float*)d_in[IX[14]];
    const float*         up_w        = (const float*)d_in[IX[15]];
    const float*         down_w      = (const float*)d_in[IX[16]];
    const float*         norm_w      = (const float*)d_in[IX[17]];
    const float*         lm_head_w   = (const float*)d_in[IX[18]];
    float* out = (float*)d_out;

    bool write_caches = (out_size >= (int)(VOC + 8u * KVDT));

    float *h_, *hn_, *q_, *kt_, *vt_, *ctx_, *gate_, *up_, *last_, *att_;
    cudaGetSymbolAddress((void**)&h_,    g_h);
    cudaGetSymbolAddress((void**)&hn_,   g_hn);
    cudaGetSymbolAddress((void**)&q_,    g_q);
    cudaGetSymbolAddress((void**)&kt_,   g_kt);
    cudaGetSymbolAddress((void**)&vt_,   g_vt);
    cudaGetSymbolAddress((void**)&ctx_,  g_ctx);
    cudaGetSymbolAddress((void**)&gate_, g_gate);
    cudaGetSymbolAddress((void**)&up_,   g_up);
    cudaGetSymbolAddress((void**)&last_, g_last);
    cudaGetSymbolAddress((void**)&att_,  g_att);

    sniff_kernel<<<1, 1>>>(input_ids, embed_q);
    embed_kernel<<<(SQ*DMODEL + 255) / 256, 256>>>(input_ids, embed_q, embed_scale, embed_zp, h_);

    for (int l = 0; l < NL; l++) {
        float* kout = out + VOC + (size_t)l * KVDT;
        float* vout = out + VOC + (size_t)(NL + l) * KVDT;
        if (!write_caches) { kout = att_; vout = att_ + KVDT; }
        const float* kcl = k_cache + (size_t)l * NKV * HD * HISTLEN;
        const float* vcl = v_cache + (size_t)l * NKV * HISTLEN * HD;

        if (write_caches) {
            copy_khist_kernel<<<(NKV*HD*HISTLEN + 255) / 256, 256>>>(kcl, kout);
            copy_vhist_kernel<<<(NKV*HISTLEN*HD + 255) / 256, 256>>>(vcl, vout);
        }

        rmsnorm_kernel<<<SQ, 256>>>(h_, ln1_w + (size_t)l * DMODEL, hn_, DMODEL);

        // QKV projections
        gemm_tc<<<dim3((NH*HD)/64,  SQ/128, 1), 256>>>(hn_, q_w + (size_t)l * DMODEL * NH * HD,  q_,
                    SQ, NH*HD,  DMODEL, DMODEL, NH*HD,  NH*HD,  0, 0, 0, 0, 0);
        gemm_tc<<<dim3((NKV*HD)/64, SQ/128, 1), 256>>>(hn_, k_w + (size_t)l * DMODEL * NKV * HD, kt_,
                    SQ, NKV*HD, DMODEL, DMODEL, NKV*HD, NKV*HD, 0, 0, 0, 0, 0);
        gemm_tc<<<dim3((NKV*HD)/64, SQ/128, 1), 256>>>(hn_, v_w + (size_t)l * DMODEL * NKV * HD, vt_,
                    SQ, NKV*HD, DMODEL, DMODEL, NKV*HD, NKV*HD, 0, 0, 0, 0, 0);

        rope_norm_kernel<<<dim3(SQ, NH + NKV), 128>>>(q_, kt_, qn_w + (size_t)l * HD, kn_w + (size_t)l * HD, kout);
        if (write_caches)
            vscatter_kernel<<<(SQ*NKV*HD + 255) / 256, 256>>>(vt_, vout);

        // scores[h] = Q_h (S x D) @ K_h (D x HIST)
        gemm_tc<<<dim3(HISTLEN/64, SQ/128, NH), 256>>>(q_, kcl, att_,
                    SQ, HISTLEN, HD, DMODEL, HISTLEN, HISTLEN,
                    (long long)HD, (long long)HD*HISTLEN, (long long)SQ*HISTLEN, 1, 0);

        att_softmax_kernel<<<dim3(SQ, NH), 256>>>(att_);

        // ctx[h] = P_h (S x HIST) @ V_h (HIST x D)
        gemm_tc<<<dim3(HD/64, SQ/128, NH), 256>>>(att_, vcl, ctx_,
                    SQ, HD, HISTLEN, HISTLEN, HD, DMODEL,
                    (long long)SQ*HISTLEN, (long long)HISTLEN*HD, (long long)HD, 1, 0);

        // O projection (residual add)
        gemm_tc<<<dim3(DMODEL/64, SQ/128, 1), 256>>>(ctx_, o_w + (size_t)l * NH * HD * DMODEL, h_,
                    SQ, DMODEL, NH*HD, NH*HD, DMODEL, DMODEL, 0, 0, 0, 0, 1);

        rmsnorm_kernel<<<SQ, 256>>>(h_, ln2_w + (size_t)l * DMODEL, hn_, DMODEL);

        gemm_tc<<<dim3(FFD/64, SQ/128, 1), 256>>>(hn_, gate_w + (size_t)l * DMODEL * FFD, gate_,
                    SQ, FFD, DMODEL, DMODEL, FFD, FFD, 0, 0, 0, 0, 0);
        gemm_tc<<<dim3(FFD/64, SQ/128, 1), 256>>>(hn_, up_w   + (size_t)l * DMODEL * FFD, up_,
                    SQ, FFD, DMODEL, DMODEL, FFD, FFD, 0, 0, 0, 0, 0);
        silu_mul_kernel<<<(SQ*FFD + 255) / 256, 256>>>(gate_, up_, gate_, SQ*FFD);
        gemm_tc<<<dim3(DMODEL/64, SQ/128, 1), 256>>>(gate_, down_w + (size_t)l * FFD * DMODEL, h_,
                    SQ, DMODEL, FFD, FFD, DMODEL, DMODEL, 0, 0, 0, 0, 1);
    }

    rmsnorm_kernel<<<1, 256>>>(h_ + (size_t)(SQ - 1) * DMODEL, norm_w, last_, DMODEL);
    lmhead_kernel<<<VOC / 256, 256>>>(last_, lm_head_w, out);
}

// round 13
// speedup vs baseline: 1.4055x; 1.3505x over previous
#include <cuda_runtime.h>
#include <cuda_bf16.h>
#include <cuda_fp16.h>
#include <math.h>
#include <stdint.h>

// ---------------- problem constants ----------------
#define SQ      1024        // S (new tokens)
#define DMODEL  2048
#define NH      16
#define NKV     8
#define HD      128
#define FFD     8192
#define NL      4
#define HISTLEN 1024
#define TTOT    2048        // HIST + S
#define VOC     32000
#define KVDT    (NKV*HD*TTOT)   // elements of one k (or v) cache output: 2097152

// ---------------- scratch (device globals; allocation-free) ----------------
__device__ float g_h[SQ*DMODEL];
__device__ float g_hn[SQ*DMODEL];
__device__ float g_q[SQ*NH*HD];
__device__ float g_kt[SQ*NKV*HD];
__device__ float g_vt[SQ*NKV*HD];
__device__ float g_ctx[SQ*NH*HD];
__device__ float g_gate[SQ*FFD];
__device__ float g_up[SQ*FFD];
__device__ float g_last[DMODEL];
__device__ float g_att[(size_t)NH*SQ*HISTLEN];   // 64MB attention scores/probs
__device__ int   g_idmode;   // 0=i32 1=i64 2=f32
__device__ int   g_eqmode;   // 0=u8  1=f32 2=i32

// ---------------- dtype sniffing (data-dependent => deterministic) ----------------
__global__ void sniff_kernel(const void* ids_raw, const void* eq_raw)
{
    if (threadIdx.x != 0 || blockIdx.x != 0) return;

    const int* ii = (const int*)ids_raw;
    bool i64ok = true;
    for (int i = 0; i < 128; i++) {
        int lo = ii[2*i], hi = ii[2*i + 1];
        if (hi != 0 || lo < 0 || lo >= VOC) { i64ok = false; break; }
    }
    if (i64ok) { g_idmode = 1; }
    else {
        bool i32ok = true;
        for (int i = 0; i < 256; i++) {
            int v = ii[i];
            if (v < 0 || v >= VOC) { i32ok = false; break; }
        }
        if (i32ok) g_idmode = 0;
        else {
            const float* ff = (const float*)ids_raw;
            bool f32ok = true;
            for (int i = 0; i < 256; i++) {
                float v = ff[i];
                if (!(v >= 0.f && v < (float)VOC && v == rintf(v))) { f32ok = false; break; }
            }
            g_idmode = f32ok ? 2 : 0;
        }
    }

    const float* ef = (const float*)eq_raw;
    bool ef32 = true;
    for (int i = 0; i < 256; i++) {
        float v = ef[i];
        if (!(v >= 0.f && v <= 255.f && v == rintf(v))) { ef32 = false; break; }
    }
    if (ef32) { g_eqmode = 1; }
    else {
        const int* ei = (const int*)eq_raw;
        bool ei32 = true;
        for (int i = 0; i < 256; i++) {
            int v = ei[i];
            if (v < 0 || v > 255) { ei32 = false; break; }
        }
        g_eqmode = ei32 ? 2 : 0;
    }
}

// ---------------- embedding dequant (dtype-agnostic) ----------------
__global__ void embed_kernel(const void* __restrict__ ids_raw,
                             const void* __restrict__ eq_raw,
                             const float* __restrict__ sc,
                             const float* __restrict__ zp,
                             float* __restrict__ h)
{
    int idx = blockIdx.x * blockDim.x + threadIdx.x;
    if (idx >= SQ*DMODEL) return;
    int s = idx >> 11;
    int c = idx & 2047;
    int idm = g_idmode;
    int id;
    if (idm == 0)      id = ((const int*)ids_raw)[s];
    else if (idm == 1) id = (int)((const long long*)ids_raw)[s];
    else               id = (int)((const float*)ids_raw)[s];
    size_t off = (size_t)id * DMODEL + c;
    int em = g_eqmode;
    float qv;
    if (em == 0)      qv = (float)((const unsigned char*)eq_raw)[off];
    else if (em == 1) qv = ((const float*)eq_raw)[off];
    else              qv = (float)((const int*)eq_raw)[off];
    h[idx] = qv * sc[id] + zp[id];
}

// ---------------- rmsnorm (one block per row) ----------------
__global__ void rmsnorm_kernel(const float* __restrict__ x, const float* __restrict__ w,
                               float* __restrict__ out, int dim)
{
    int row = blockIdx.x;
    const float* xr = x + (size_t)row * dim;
    float ss = 0.f;
    for (int i = threadIdx.x; i < dim; i += blockDim.x) {
        float v = xr[i]; ss += v * v;
    }
#pragma unroll
    for (int o = 16; o > 0; o >>= 1) ss += __shfl_xor_sync(0xffffffffu, ss, o);
    __shared__ float wsum[8];
    if ((threadIdx.x & 31) == 0) wsum[threadIdx.x >> 5] = ss;
    __syncthreads();
    float tot = 0.f;
    int nw = blockDim.x >> 5;
    for (int k = 0; k < nw; k++) tot += wsum[k];
    float inv = rsqrtf(tot / (float)dim + 1e-6f);
    float* orow = out + (size_t)row * dim;
    for (int i = threadIdx.x; i < dim; i += blockDim.x)
        orow[i] = w[i] * xr[i] * inv;
}

// ---------------- fp16 split helpers ----------------
// pack two floats into hi-fp16x2 (returned) and lo-fp16x2 (out param)
__device__ __forceinline__ uint32_t pack_split(float a, float b, uint32_t& lo)
{
    __half ha = __float2half_rn(a), hb = __float2half_rn(b);
    __half la = __float2half_rn(a - __half2float(ha));
    __half lb = __float2half_rn(b - __half2float(hb));
    lo = ((uint32_t)__half_as_ushort(lb) << 16) | __half_as_ushort(la);
    return ((uint32_t)__half_as_ushort(hb) << 16) | __half_as_ushort(ha);
}

#define MMA_F16(C0,C1,C2,C3, A0,A1,A2,A3, B0,B1) \
    asm volatile("mma.sync.aligned.m16n8k16.row.col.f32.f16.f16.f32 " \
        "{%0,%1,%2,%3}, {%4,%5,%6,%7}, {%8,%9}, {%0,%1,%2,%3};" \
        : "+f"(C0), "+f"(C1), "+f"(C2), "+f"(C3) \
        : "r"(A0), "r"(A1), "r"(A2), "r"(A3), "r"(B0), "r"(B1))

// ---------------- tensor-core strided/batched GEMM (3x fp16-split, fp32-accurate) ----
// C[M,N] (+)= A[M,K] @ B[K,N]; element strides lda/ldb/ldc.
// Per-z offsets: A += z*saz, B += (z>>zdivB)*sbz, C += z*scz.
// BM=128 BN=128 BK=32, 256 threads (8 warps, 4x2), warp tile 32x64.
// smem rows padded to 40 halves (20 words): fragment LDS bank pattern
// (20g+t) mod 32 is all-distinct -> conflict-free.
#define ROWW 20   // words per smem row (40 halves: 32 data + 8 pad)
__global__ void __launch_bounds__(256) gemm_tc(
    const float* __restrict__ A, const float* __restrict__ B, float* __restrict__ C,
    int M, int N, int K, int lda, int ldb, int ldc,
    long long saz, long long sbz, long long scz, int zdivB, int beta)
{
    A += (long long)blockIdx.z * saz;
    B += (long long)(blockIdx.z >> zdivB) * sbz;
    C += (long long)blockIdx.z * scz;

    __shared__ uint32_t Ah[128 * ROWW];   // [m][k-pair] hi
    __shared__ uint32_t Al[128 * ROWW];   // lo
    __shared__ uint32_t Bh[128 * ROWW];   // [n][k-pair] hi
    __shared__ uint32_t Bl[128 * ROWW];   // lo

    int tid  = threadIdx.x;
    int lane = tid & 31;
    int warp = tid >> 5;
    int wm = warp & 3;          // m slab of 32
    int wn = warp >> 2;         // n slab of 64
    int g = lane >> 2;          // 0..7
    int t = lane & 3;           // 0..3
    int m0 = blockIdx.y * 128;
    int n0 = blockIdx.x * 128;

    float acc[2][8][4];
#pragma unroll
    for (int i = 0; i < 2; i++)
#pragma unroll
        for (int j = 0; j < 8; j++)
#pragma unroll
            for (int k = 0; k < 4; k++) acc[i][j][k] = 0.f;

    int bkg = tid >> 5;         // k-group 0..7 for B loads
    int bn  = tid & 31;         // base n for B loads

    for (int kk = 0; kk < K; kk += 32) {
        // ---- A tile 128x32 -> smem [m][k] split ----
#pragma unroll
        for (int i = 0; i < 4; i++) {
            int f = tid + i * 256;          // float4 id 0..1023
            int m = f >> 3;
            int kq = (f & 7) << 2;
            float4 v = *(const float4*)(A + (size_t)(m0 + m) * lda + kk + kq);
            uint32_t l0, l1;
            uint32_t h0 = pack_split(v.x, v.y, l0);
            uint32_t h1 = pack_split(v.z, v.w, l1);
            *(uint2*)&Ah[m * ROWW + (kq >> 1)] = make_uint2(h0, h1);
            *(uint2*)&Al[m * ROWW + (kq >> 1)] = make_uint2(l0, l1);
        }
        // ---- B tile 32x128 -> smem [n][k] split (transpose via strided reads) ----
#pragma unroll
        for (int i = 0; i < 4; i++) {
            int n = bn + 32 * i;
            const float* bp = B + (size_t)(kk + bkg * 4) * ldb + n0 + n;
            float b0 = bp[0];
            float b1 = bp[ldb];
            float b2 = bp[2 * (size_t)ldb];
            float b3 = bp[3 * (size_t)ldb];
            uint32_t l0, l1;
            uint32_t h0 = pack_split(b0, b1, l0);
            uint32_t h1 = pack_split(b2, b3, l1);
            *(uint2*)&Bh[n * ROWW + bkg * 2] = make_uint2(h0, h1);
            *(uint2*)&Bl[n * ROWW + bkg * 2] = make_uint2(l0, l1);
        }
        __syncthreads();

#pragma unroll
        for (int ks = 0; ks < 2; ks++) {    // two k16 chunks
            int kw = ks * 8;                // word offset
            uint32_t ah[2][4], al[2][4];
#pragma unroll
            for (int mt = 0; mt < 2; mt++) {
                int base = (wm * 32 + mt * 16 + g) * ROWW + kw + t;
                ah[mt][0] = Ah[base];
                ah[mt][1] = Ah[base + 8 * ROWW];
                ah[mt][2] = Ah[base + 4];
                ah[mt][3] = Ah[base + 8 * ROWW + 4];
                al[mt][0] = Al[base];
                al[mt][1] = Al[base + 8 * ROWW];
                al[mt][2] = Al[base + 4];
                al[mt][3] = Al[base + 8 * ROWW + 4];
            }
#pragma unroll
            for (int nt = 0; nt < 8; nt++) {
                int bbase = (wn * 64 + nt * 8 + g) * ROWW + kw + t;
                uint32_t bh0 = Bh[bbase], bh1 = Bh[bbase + 4];
                uint32_t bl0 = Bl[bbase], bl1 = Bl[bbase + 4];
#pragma unroll
                for (int mt = 0; mt < 2; mt++) {
                    float* c4 = acc[mt][nt];
                    MMA_F16(c4[0], c4[1], c4[2], c4[3],
                            ah[mt][0], ah[mt][1], ah[mt][2], ah[mt][3], bh0, bh1);
                    MMA_F16(c4[0], c4[1], c4[2], c4[3],
                            ah[mt][0], ah[mt][1], ah[mt][2], ah[mt][3], bl0, bl1);
                    MMA_F16(c4[0], c4[1], c4[2], c4[3],
                            al[mt][0], al[mt][1], al[mt][2], al[mt][3], bh0, bh1);
                }
            }
        }
        __syncthreads();
    }

    // ---- epilogue ----
#pragma unroll
    for (int mt = 0; mt < 2; mt++) {
        int r0 = m0 + wm * 32 + mt * 16 + g;
#pragma unroll
        for (int nt = 0; nt < 8; nt++) {
            int cb = n0 + wn * 64 + nt * 8 + 2 * t;
            float* p0 = C + (size_t)r0 * ldc + cb;
            float* p1 = C + (size_t)(r0 + 8) * ldc + cb;
            float* c4 = acc[mt][nt];
            if (beta) {
                float2 o0 = *(float2*)p0, o1 = *(float2*)p1;
                o0.x += c4[0]; o0.y += c4[1];
                o1.x += c4[2]; o1.y += c4[3];
                *(float2*)p0 = o0; *(float2*)p1 = o1;
            } else {
                *(float2*)p0 = make_float2(c4[0], c4[1]);
                *(float2*)p1 = make_float2(c4[2], c4[3]);
            }
        }
    }
}

// ---------------- RoPE + q/k rmsnorm ----------------
__global__ void rope_norm_kernel(float* __restrict__ q, const float* __restrict__ kt,
                                 const float* __restrict__ qn_w, const float* __restrict__ kn_w,
                                 float* __restrict__ kout)
{
    int s = blockIdx.x;
    int head = blockIdx.y;
    int d = threadIdx.x;
    bool isq = (head < NH);
    const float* src = isq ? (q  + (size_t)s * NH * HD + head * HD)
                           : (kt + (size_t)s * NKV * HD + (head - NH) * HD);
    float x  = src[d];
    float xp = src[(d < 64) ? d + 64 : d - 64];
    int i2 = d & 63;
    float invf = (float)exp(-log(10000.0) * ((double)(2 * i2) / 128.0));
    float ang = (float)(HISTLEN + s) * invf;
    float c  = __half2float(__float2half((float)cos((double)ang)));
    float sn = __half2float(__float2half((float)sin((double)ang)));
    float r = (d < 64) ? (x * c - xp * sn) : (x * c + xp * sn);

    float ss = r * r;
#pragma unroll
    for (int o = 16; o > 0; o >>= 1) ss += __shfl_xor_sync(0xffffffffu, ss, o);
    __shared__ float wsum[4];
    if ((d & 31) == 0) wsum[d >> 5] = ss;
    __syncthreads();
    float tot = wsum[0] + wsum[1] + wsum[2] + wsum[3];
    float inv = rsqrtf(tot * (1.0f / 128.0f) + 1e-6f);
    float w = isq ? qn_w[d] : kn_w[d];
    float out = w * r * inv;
    if (isq) {
        q[(size_t)s * NH * HD + head * HD + d] = out;
    } else {
        int kvh = head - NH;
        kout[(size_t)kvh * HD * TTOT + (size_t)d * TTOT + HISTLEN + s] = out;
    }
}

// ---------------- masked softmax over scores row ----------------
__global__ void att_softmax_kernel(float* __restrict__ P)
{
    int s = blockIdx.x;
    int h = blockIdx.y;
    float* row = P + ((size_t)h * SQ + s) * HISTLEN;
    int n = s + 1;
    int tid = threadIdx.x;
    __shared__ float red[8];

    float mx = -1e30f;
    for (int t = tid; t < n; t += 256) mx = fmaxf(mx, row[t]);
#pragma unroll
    for (int o = 16; o > 0; o >>= 1) mx = fmaxf(mx, __shfl_xor_sync(0xffffffffu, mx, o));
    if ((tid & 31) == 0) red[tid >> 5] = mx;
    __syncthreads();
    mx = fmaxf(fmaxf(fmaxf(red[0], red[1]), fmaxf(red[2], red[3])),
               fmaxf(fmaxf(red[4], red[5]), fmaxf(red[6], red[7])));

    float sum = 0.f;
    for (int t = tid; t < n; t += 256) {
        float p = __expf(row[t] - mx);
        row[t] = p;
        sum += p;
    }
#pragma unroll
    for (int o = 16; o > 0; o >>= 1) sum += __shfl_xor_sync(0xffffffffu, sum, o);
    __syncthreads();
    if ((tid & 31) == 0) red[tid >> 5] = sum;
    __syncthreads();
    sum = red[0] + red[1] + red[2] + red[3] + red[4] + red[5] + red[6] + red[7];
    float inv = 1.f / sum;
    for (int t = tid; t < HISTLEN; t += 256)
        row[t] = (t < n) ? row[t] * inv : 0.f;
}

// ---------------- cache assembly ----------------
__global__ void copy_khist_kernel(const float* __restrict__ src, float* __restrict__ dst)
{
    int idx = blockIdx.x * blockDim.x + threadIdx.x;
    if (idx >= NKV * HD * HISTLEN) return;
    int t = idx & (HISTLEN - 1);
    int row = idx >> 10;
    dst[(size_t)row * TTOT + t] = src[idx];
}

__global__ void copy_vhist_kernel(const float* __restrict__ src, float* __restrict__ dst)
{
    int idx = blockIdx.x * blockDim.x + threadIdx.x;
    if (idx >= NKV * HISTLEN * HD) return;
    int within = idx & (HISTLEN * HD - 1);
    int kv = idx >> 17;
    dst[(size_t)kv * TTOT * HD + within] = src[idx];
}

__global__ void vscatter_kernel(const float* __restrict__ vt, float* __restrict__ dst)
{
    int idx = blockIdx.x * blockDim.x + threadIdx.x;
    if (idx >= SQ * NKV * HD) return;
    int d = idx & 127;
    int kv = (idx >> 7) & 7;
    int s = idx >> 10;
    dst[(size_t)kv * TTOT * HD + (size_t)(HISTLEN + s) * HD + d] = vt[idx];
}

// ---------------- silu(gate)*up ----------------
__global__ void silu_mul_kernel(const float* __restrict__ g, const float* __restrict__ u,
                                float* __restrict__ o, int n)
{
    int i = blockIdx.x * blockDim.x + threadIdx.x;
    if (i < n) {
        float x = g[i];
        o[i] = (x / (1.f + expf(-x))) * u[i];
    }
}

// ---------------- lm head GEMV ----------------
__global__ void lmhead_kernel(const float* __restrict__ x, const float* __restrict__ W,
                              float* __restrict__ out)
{
    __shared__ float xs[256];
    int v = blockIdx.x * 256 + threadIdx.x;
    float acc = 0.f;
    for (int k0 = 0; k0 < DMODEL; k0 += 256) {
        xs[threadIdx.x] = x[k0 + threadIdx.x];
        __syncthreads();
#pragma unroll 16
        for (int k = 0; k < 256; k++)
            acc += xs[k] * W[(size_t)(k0 + k) * VOC + v];
        __syncthreads();
    }
    if (v < VOC) out[v] = acc;
}

// ---------------- host launcher ----------------
extern "C" void kernel_launch(void* const* d_in, const int* in_sizes, int n_in,
                              void* d_out, int out_size)
{
    int IX[19];
    for (int i = 0; i < 19; i++) IX[i] = i;
    if (n_in >= 19 && in_sizes[0] != 1024) {
        const int amap[19] = {5, 6, 17, 1, 2, 3, 9, 14, 7, 18, 15, 8, 13, 10, 4, 16, 0, 12, 11};
        for (int i = 0; i < 19; i++) IX[i] = amap[i];
    }

    const void*          input_ids   = d_in[IX[0]];
    const float*         k_cache     = (const float*)d_in[IX[1]];
    const float*         v_cache     = (const float*)d_in[IX[2]];
    const void*          embed_q     = d_in[IX[3]];
    const float*         embed_scale = (const float*)d_in[IX[4]];
    const float*         embed_zp    = (const float*)d_in[IX[5]];
    const float*         ln1_w       = (const float*)d_in[IX[6]];
    const float*         q_w         = (const float*)d_in[IX[7]];
    const float*         k_w         = (const float*)d_in[IX[8]];
    const float*         v_w         = (const float*)d_in[IX[9]];
    const float*         qn_w        = (const float*)d_in[IX[10]];
    const float*         kn_w        = (const float*)d_in[IX[11]];
    const float*         o_w         = (const float*)d_in[IX[12]];
    const float*         ln2_w       = (const float*)d_in[IX[13]];
    const float*         gate_w      = (const float*)d_in[IX[14]];
    const float*         up_w        = (const float*)d_in[IX[15]];
    const float*         down_w      = (const float*)d_in[IX[16]];
    const float*         norm_w      = (const float*)d_in[IX[17]];
    const float*         lm_head_w   = (const float*)d_in[IX[18]];
    float* out = (float*)d_out;

    bool write_caches = (out_size >= (int)(VOC + 8u * KVDT));

    float *h_, *hn_, *q_, *kt_, *vt_, *ctx_, *gate_, *up_, *last_, *att_;
    cudaGetSymbolAddress((void**)&h_,    g_h);
    cudaGetSymbolAddress((void**)&hn_,   g_hn);
    cudaGetSymbolAddress((void**)&q_,    g_q);
    cudaGetSymbolAddress((void**)&kt_,   g_kt);
    cudaGetSymbolAddress((void**)&vt_,   g_vt);
    cudaGetSymbolAddress((void**)&ctx_,  g_ctx);
    cudaGetSymbolAddress((void**)&gate_, g_gate);
    cudaGetSymbolAddress((void**)&up_,   g_up);
    cudaGetSymbolAddress((void**)&last_, g_last);
    cudaGetSymbolAddress((void**)&att_,  g_att);

    sniff_kernel<<<1, 1>>>(input_ids, embed_q);
    embed_kernel<<<(SQ*DMODEL + 255) / 256, 256>>>(input_ids, embed_q, embed_scale, embed_zp, h_);

    for (int l = 0; l < NL; l++) {
        float* kout = out + VOC + (size_t)l * KVDT;
        float* vout = out + VOC + (size_t)(NL + l) * KVDT;
        if (!write_caches) { kout = att_; vout = att_ + KVDT; }
        const float* kcl = k_cache + (size_t)l * NKV * HD * HISTLEN;
        const float* vcl = v_cache + (size_t)l * NKV * HISTLEN * HD;

        if (write_caches) {
            copy_khist_kernel<<<(NKV*HD*HISTLEN + 255) / 256, 256>>>(kcl, kout);
            copy_vhist_kernel<<<(NKV*HISTLEN*HD + 255) / 256, 256>>>(vcl, vout);
        }

        rmsnorm_kernel<<<SQ, 256>>>(h_, ln1_w + (size_t)l * DMODEL, hn_, DMODEL);

        // QKV projections
        gemm_tc<<<dim3((NH*HD)/128,  SQ/128, 1), 256>>>(hn_, q_w + (size_t)l * DMODEL * NH * HD,  q_,
                    SQ, NH*HD,  DMODEL, DMODEL, NH*HD,  NH*HD,  0, 0, 0, 0, 0);
        gemm_tc<<<dim3((NKV*HD)/128, SQ/128, 1), 256>>>(hn_, k_w + (size_t)l * DMODEL * NKV * HD, kt_,
                    SQ, NKV*HD, DMODEL, DMODEL, NKV*HD, NKV*HD, 0, 0, 0, 0, 0);
        gemm_tc<<<dim3((NKV*HD)/128, SQ/128, 1), 256>>>(hn_, v_w + (size_t)l * DMODEL * NKV * HD, vt_,
                    SQ, NKV*HD, DMODEL, DMODEL, NKV*HD, NKV*HD, 0, 0, 0, 0, 0);

        rope_norm_kernel<<<dim3(SQ, NH + NKV), 128>>>(q_, kt_, qn_w + (size_t)l * HD, kn_w + (size_t)l * HD, kout);
        if (write_caches)
            vscatter_kernel<<<(SQ*NKV*HD + 255) / 256, 256>>>(vt_, vout);

        // scores[h] = Q_h (S x D) @ K_h (D x HIST)
        gemm_tc<<<dim3(HISTLEN/128, SQ/128, NH), 256>>>(q_, kcl, att_,
                    SQ, HISTLEN, HD, DMODEL, HISTLEN, HISTLEN,
                    (long long)HD, (long long)HD*HISTLEN, (long long)SQ*HISTLEN, 1, 0);

        att_softmax_kernel<<<dim3(SQ, NH), 256>>>(att_);

        // ctx[h] = P_h (S x HIST) @ V_h (HIST x D)
        gemm_tc<<<dim3(HD/128, SQ/128, NH), 256>>>(att_, vcl, ctx_,
                    SQ, HD, HISTLEN, HISTLEN, HD, DMODEL,
                    (long long)SQ*HISTLEN, (long long)HISTLEN*HD, (long long)HD, 1, 0);

        // O projection (residual add)
        gemm_tc<<<dim3(DMODEL/128, SQ/128, 1), 256>>>(ctx_, o_w + (size_t)l * NH * HD * DMODEL, h_,
                    SQ, DMODEL, NH*HD, NH*HD, DMODEL, DMODEL, 0, 0, 0, 0, 1);

        rmsnorm_kernel<<<SQ, 256>>>(h_, ln2_w + (size_t)l * DMODEL, hn_, DMODEL);

        gemm_tc<<<dim3(FFD/128, SQ/128, 1), 256>>>(hn_, gate_w + (size_t)l * DMODEL * FFD, gate_,
                    SQ, FFD, DMODEL, DMODEL, FFD, FFD, 0, 0, 0, 0, 0);
        gemm_tc<<<dim3(FFD/128, SQ/128, 1), 256>>>(hn_, up_w   + (size_t)l * DMODEL * FFD, up_,
                    SQ, FFD, DMODEL, DMODEL, FFD, FFD, 0, 0, 0, 0, 0);
        silu_mul_kernel<<<(SQ*FFD + 255) / 256, 256>>>(gate_, up_, gate_, SQ*FFD);
        gemm_tc<<<dim3(DMODEL/128, SQ/128, 1), 256>>>(gate_, down_w + (size_t)l * FFD * DMODEL, h_,
                    SQ, DMODEL, FFD, FFD, DMODEL, DMODEL, 0, 0, 0, 0, 1);
    }

    rmsnorm_kernel<<<1, 256>>>(h_ + (size_t)(SQ - 1) * DMODEL, norm_w, last_, DMODEL);
    lmhead_kernel<<<VOC / 256, 256>>>(last_, lm_head_w, out);
}

// round 14
// speedup vs baseline: 1.5093x; 1.0739x over previous
#include <cuda_runtime.h>
#include <cuda_bf16.h>
#include <cuda_fp16.h>
#include <math.h>
#include <stdint.h>

// ---------------- problem constants ----------------
#define SQ      1024
#define DMODEL  2048
#define NH      16
#define NKV     8
#define HD      128
#define FFD     8192
#define NL      4
#define HISTLEN 1024
#define TTOT    2048
#define VOC     32000
#define KVDT    (NKV*HD*TTOT)

// ---------------- fp32 scratch ----------------
__device__ float g_h[SQ*DMODEL];
__device__ float g_q[SQ*NH*HD];
__device__ float g_kt[SQ*NKV*HD];
__device__ float g_vt[SQ*NKV*HD];
__device__ float g_gate[SQ*FFD];
__device__ float g_up[SQ*FFD];
__device__ float g_last[DMODEL];
__device__ float g_att[(size_t)NH*SQ*HISTLEN];   // 64MB scores
__device__ int   g_idmode;
__device__ int   g_eqmode;

// ---------------- pre-split fp16 hi/lo buffers (uint = fp16x2 pair along K) ----
__device__ unsigned g_wqh[NL*2048*1024], g_wql[NL*2048*1024];
__device__ unsigned g_wkh[NL*1024*1024], g_wkl[NL*1024*1024];
__device__ unsigned g_wvh[NL*1024*1024], g_wvl[NL*1024*1024];
__device__ unsigned g_woh[NL*2048*1024], g_wol[NL*2048*1024];
__device__ unsigned g_wgh[NL*8192*1024], g_wgl[NL*8192*1024];
__device__ unsigned g_wuh[NL*8192*1024], g_wul[NL*8192*1024];
__device__ unsigned g_wdh[NL*2048*4096], g_wdl[NL*2048*4096];
__device__ unsigned g_kth[NL*NKV*65536], g_ktl[NL*NKV*65536];  // [t][d] per kv
__device__ unsigned g_vth[NL*NKV*65536], g_vtl[NL*NKV*65536];  // [d][t] per kv
__device__ unsigned g_hnh[SQ*1024],  g_hnl[SQ*1024];
__device__ unsigned g_qh[SQ*1024],   g_ql[SQ*1024];
__device__ unsigned g_Ph[(size_t)NH*SQ*512], g_Pl[(size_t)NH*SQ*512];
__device__ unsigned g_ctxh[SQ*1024], g_ctxl[SQ*1024];
__device__ unsigned g_guh[SQ*4096],  g_gul[SQ*4096];

// ---------------- helpers ----------------
__device__ __forceinline__ uint32_t pack_split(float a, float b, uint32_t& lo)
{
    __half ha = __float2half_rn(a), hb = __float2half_rn(b);
    __half la = __float2half_rn(a - __half2float(ha));
    __half lb = __float2half_rn(b - __half2float(hb));
    lo = ((uint32_t)__half_as_ushort(lb) << 16) | __half_as_ushort(la);
    return ((uint32_t)__half_as_ushort(hb) << 16) | __half_as_ushort(ha);
}

// ---------------- dtype sniffing ----------------
__global__ void sniff_kernel(const void* ids_raw, const void* eq_raw)
{
    if (threadIdx.x != 0 || blockIdx.x != 0) return;
    const int* ii = (const int*)ids_raw;
    bool i64ok = true;
    for (int i = 0; i < 128; i++) {
        int lo = ii[2*i], hi = ii[2*i + 1];
        if (hi != 0 || lo < 0 || lo >= VOC) { i64ok = false; break; }
    }
    if (i64ok) { g_idmode = 1; }
    else {
        bool i32ok = true;
        for (int i = 0; i < 256; i++) {
            int v = ii[i];
            if (v < 0 || v >= VOC) { i32ok = false; break; }
        }
        if (i32ok) g_idmode = 0;
        else {
            const float* ff = (const float*)ids_raw;
            bool f32ok = true;
            for (int i = 0; i < 256; i++) {
                float v = ff[i];
                if (!(v >= 0.f && v < (float)VOC && v == rintf(v))) { f32ok = false; break; }
            }
            g_idmode = f32ok ? 2 : 0;
        }
    }
    const float* ef = (const float*)eq_raw;
    bool ef32 = true;
    for (int i = 0; i < 256; i++) {
        float v = ef[i];
        if (!(v >= 0.f && v <= 255.f && v == rintf(v))) { ef32 = false; break; }
    }
    if (ef32) { g_eqmode = 1; }
    else {
        const int* ei = (const int*)eq_raw;
        bool ei32 = true;
        for (int i = 0; i < 256; i++) {
            int v = ei[i];
            if (v < 0 || v > 255) { ei32 = false; break; }
        }
        g_eqmode = ei32 ? 2 : 0;
    }
}

// ---------------- embedding ----------------
__global__ void embed_kernel(const void* __restrict__ ids_raw,
                             const void* __restrict__ eq_raw,
                             const float* __restrict__ sc,
                             const float* __restrict__ zp,
                             float* __restrict__ h)
{
    int idx = blockIdx.x * blockDim.x + threadIdx.x;
    if (idx >= SQ*DMODEL) return;
    int s = idx >> 11;
    int c = idx & 2047;
    int idm = g_idmode;
    int id;
    if (idm == 0)      id = ((const int*)ids_raw)[s];
    else if (idm == 1) id = (int)((const long long*)ids_raw)[s];
    else               id = (int)((const float*)ids_raw)[s];
    size_t off = (size_t)id * DMODEL + c;
    int em = g_eqmode;
    float qv;
    if (em == 0)      qv = (float)((const unsigned char*)eq_raw)[off];
    else if (em == 1) qv = ((const float*)eq_raw)[off];
    else              qv = (float)((const int*)eq_raw)[off];
    h[idx] = qv * sc[id] + zp[id];
}

// ---------------- transpose-split: in[z][K][N] fp32 -> oh/ol[z][N][K/2] -----
// grid (N/32, K/64, Z), 256 threads
__global__ void wsplit_kernel(const float* __restrict__ in,
                              unsigned* __restrict__ oh, unsigned* __restrict__ ol,
                              int K, int N, long long inz, long long outz)
{
    in += (long long)blockIdx.z * inz;
    oh += (long long)blockIdx.z * outz;
    ol += (long long)blockIdx.z * outz;
    __shared__ float s[64][33];
    int n0 = blockIdx.x * 32, k0 = blockIdx.y * 64;
    int tid = threadIdx.x;
#pragma unroll
    for (int i = 0; i < 8; i++) {
        int f = tid + i * 256;
        int k = f >> 5, n = f & 31;
        s[k][n] = in[(size_t)(k0 + k) * N + n0 + n];
    }
    __syncthreads();
    int Ku = K >> 1;
#pragma unroll
    for (int i = 0; i < 4; i++) {
        int f = tid + i * 256;
        int n = f >> 5, ku = f & 31;
        uint32_t lo_;
        uint32_t hi_ = pack_split(s[2*ku][n], s[2*ku + 1][n], lo_);
        size_t o = (size_t)(n0 + n) * Ku + (k0 >> 1) + ku;
        oh[o] = hi_; ol[o] = lo_;
    }
}

// ---------------- rmsnorm -> split pairs ----------------
__global__ void rmsnorm_split_kernel(const float* __restrict__ x, const float* __restrict__ w,
                                     unsigned* __restrict__ oh, unsigned* __restrict__ ol, int dim)
{
    int row = blockIdx.x;
    const float* xr = x + (size_t)row * dim;
    float ss = 0.f;
    for (int i = threadIdx.x; i < dim; i += blockDim.x) {
        float v = xr[i]; ss += v * v;
    }
#pragma unroll
    for (int o = 16; o > 0; o >>= 1) ss += __shfl_xor_sync(0xffffffffu, ss, o);
    __shared__ float wsum[8];
    if ((threadIdx.x & 31) == 0) wsum[threadIdx.x >> 5] = ss;
    __syncthreads();
    float tot = 0.f;
    for (int k = 0; k < 8; k++) tot += wsum[k];
    float inv = rsqrtf(tot / (float)dim + 1e-6f);
    int du = dim >> 1;
    for (int i = threadIdx.x; i < du; i += blockDim.x) {
        float a = w[2*i] * xr[2*i] * inv;
        float b = w[2*i + 1] * xr[2*i + 1] * inv;
        uint32_t lo_;
        uint32_t hi_ = pack_split(a, b, lo_);
        oh[(size_t)row * du + i] = hi_;
        ol[(size_t)row * du + i] = lo_;
    }
}

// ---------------- fp32 rmsnorm (final norm only) ----------------
__global__ void rmsnorm_kernel(const float* __restrict__ x, const float* __restrict__ w,
                               float* __restrict__ out, int dim)
{
    int row = blockIdx.x;
    const float* xr = x + (size_t)row * dim;
    float ss = 0.f;
    for (int i = threadIdx.x; i < dim; i += blockDim.x) {
        float v = xr[i]; ss += v * v;
    }
#pragma unroll
    for (int o = 16; o > 0; o >>= 1) ss += __shfl_xor_sync(0xffffffffu, ss, o);
    __shared__ float wsum[8];
    if ((threadIdx.x & 31) == 0) wsum[threadIdx.x >> 5] = ss;
    __syncthreads();
    float tot = 0.f;
    int nw = blockDim.x >> 5;
    for (int k = 0; k < nw; k++) tot += wsum[k];
    float inv = rsqrtf(tot / (float)dim + 1e-6f);
    float* orow = out + (size_t)row * dim;
    for (int i = threadIdx.x; i < dim; i += blockDim.x)
        orow[i] = w[i] * xr[i] * inv;
}

// ---------------- mma macro ----------------
#define MMA_F16(C0,C1,C2,C3, A0,A1,A2,A3, B0,B1) \
    asm volatile("mma.sync.aligned.m16n8k16.row.col.f32.f16.f16.f32 " \
        "{%0,%1,%2,%3}, {%4,%5,%6,%7}, {%8,%9}, {%0,%1,%2,%3};" \
        : "+f"(C0), "+f"(C1), "+f"(C2), "+f"(C3) \
        : "r"(A0), "r"(A1), "r"(A2), "r"(A3), "r"(B0), "r"(B1))

// ---------------- pre-split GEMM: C (+)= A @ B^T_presplit ----------------
// A: hi/lo uint arrays [M][Ku], B: [N][Ku] (pair-packed along K).
// mode 0: C store fp32; 1: C += ; 2: split-store to Oh/Ol (ldc in uints).
#define ROWW 20
__global__ void __launch_bounds__(256) gemm_sp(
    const unsigned* __restrict__ Ah, const unsigned* __restrict__ Al,
    const unsigned* __restrict__ Bh, const unsigned* __restrict__ Bl,
    float* __restrict__ C, unsigned* __restrict__ Oh, unsigned* __restrict__ Ol,
    int N, int Ku, int ldau, int ldbu, int ldc,
    long long sazu, long long sbzu, long long sczu, int zdivB, int mode)
{
    Ah += (long long)blockIdx.z * sazu;
    Al += (long long)blockIdx.z * sazu;
    long long bz = (long long)(blockIdx.z >> zdivB) * sbzu;
    Bh += bz; Bl += bz;
    if (mode == 2) { Oh += (long long)blockIdx.z * sczu; Ol += (long long)blockIdx.z * sczu; }
    else           { C  += (long long)blockIdx.z * sczu; }

    __shared__ unsigned Ahs[128 * ROWW], Als[128 * ROWW];
    __shared__ unsigned Bhs[128 * ROWW], Bls[128 * ROWW];

    int tid  = threadIdx.x;
    int lane = tid & 31;
    int warp = tid >> 5;
    int wm = warp & 3;
    int wn = warp >> 2;
    int g = lane >> 2;
    int t = lane & 3;
    int m0 = blockIdx.y * 128;
    int n0 = blockIdx.x * 128;

    float acc[2][8][4];
#pragma unroll
    for (int i = 0; i < 2; i++)
#pragma unroll
        for (int j = 0; j < 8; j++)
#pragma unroll
            for (int k = 0; k < 4; k++) acc[i][j][k] = 0.f;

    for (int ku0 = 0; ku0 < Ku; ku0 += 16) {
#pragma unroll
        for (int i = 0; i < 2; i++) {
            int f = tid + i * 256;
            int r = f >> 2;
            int q4 = (f & 3) << 2;
            const unsigned* pa = Ah + (size_t)(m0 + r) * ldau + ku0 + q4;
            const unsigned* pl = Al + (size_t)(m0 + r) * ldau + ku0 + q4;
            *(uint4*)&Ahs[r * ROWW + q4] = *(const uint4*)pa;
            *(uint4*)&Als[r * ROWW + q4] = *(const uint4*)pl;
            const unsigned* pb = Bh + (size_t)(n0 + r) * ldbu + ku0 + q4;
            const unsigned* pbl = Bl + (size_t)(n0 + r) * ldbu + ku0 + q4;
            *(uint4*)&Bhs[r * ROWW + q4] = *(const uint4*)pb;
            *(uint4*)&Bls[r * ROWW + q4] = *(const uint4*)pbl;
        }
        __syncthreads();

#pragma unroll
        for (int ks = 0; ks < 2; ks++) {
            int kw = ks * 8;
            uint32_t ah[2][4], al[2][4];
#pragma unroll
            for (int mt = 0; mt < 2; mt++) {
                int base = (wm * 32 + mt * 16 + g) * ROWW + kw + t;
                ah[mt][0] = Ahs[base];
                ah[mt][1] = Ahs[base + 8 * ROWW];
                ah[mt][2] = Ahs[base + 4];
                ah[mt][3] = Ahs[base + 8 * ROWW + 4];
                al[mt][0] = Als[base];
                al[mt][1] = Als[base + 8 * ROWW];
                al[mt][2] = Als[base + 4];
                al[mt][3] = Als[base + 8 * ROWW + 4];
            }
#pragma unroll
            for (int nt = 0; nt < 8; nt++) {
                int bbase = (wn * 64 + nt * 8 + g) * ROWW + kw + t;
                uint32_t bh0 = Bhs[bbase], bh1 = Bhs[bbase + 4];
                uint32_t bl0 = Bls[bbase], bl1 = Bls[bbase + 4];
#pragma unroll
                for (int mt = 0; mt < 2; mt++) {
                    float* c4 = acc[mt][nt];
                    MMA_F16(c4[0], c4[1], c4[2], c4[3],
                            ah[mt][0], ah[mt][1], ah[mt][2], ah[mt][3], bh0, bh1);
                    MMA_F16(c4[0], c4[1], c4[2], c4[3],
                            ah[mt][0], ah[mt][1], ah[mt][2], ah[mt][3], bl0, bl1);
                    MMA_F16(c4[0], c4[1], c4[2], c4[3],
                            al[mt][0], al[mt][1], al[mt][2], al[mt][3], bh0, bh1);
                }
            }
        }
        __syncthreads();
    }

#pragma unroll
    for (int mt = 0; mt < 2; mt++) {
        int r0 = m0 + wm * 32 + mt * 16 + g;
#pragma unroll
        for (int nt = 0; nt < 8; nt++) {
            int cb = n0 + wn * 64 + nt * 8 + 2 * t;
            float* c4 = acc[mt][nt];
            if (mode == 2) {
                uint32_t lo_;
                uint32_t hi_ = pack_split(c4[0], c4[1], lo_);
                Oh[(size_t)r0 * ldc + (cb >> 1)] = hi_;
                Ol[(size_t)r0 * ldc + (cb >> 1)] = lo_;
                hi_ = pack_split(c4[2], c4[3], lo_);
                Oh[(size_t)(r0 + 8) * ldc + (cb >> 1)] = hi_;
                Ol[(size_t)(r0 + 8) * ldc + (cb >> 1)] = lo_;
            } else {
                float* p0 = C + (size_t)r0 * ldc + cb;
                float* p1 = C + (size_t)(r0 + 8) * ldc + cb;
                if (mode == 1) {
                    float2 o0 = *(float2*)p0, o1 = *(float2*)p1;
                    o0.x += c4[0]; o0.y += c4[1];
                    o1.x += c4[2]; o1.y += c4[3];
                    *(float2*)p0 = o0; *(float2*)p1 = o1;
                } else {
                    *(float2*)p0 = make_float2(c4[0], c4[1]);
                    *(float2*)p1 = make_float2(c4[2], c4[3]);
                }
            }
        }
    }
}

// ---------------- RoPE + q/k rmsnorm (q -> split pairs, k -> cache) ----------
__global__ void rope_norm_kernel(const float* __restrict__ q, const float* __restrict__ kt,
                                 const float* __restrict__ qn_w, const float* __restrict__ kn_w,
                                 float* __restrict__ kout,
                                 unsigned* __restrict__ qh, unsigned* __restrict__ ql)
{
    int s = blockIdx.x;
    int head = blockIdx.y;
    int d = threadIdx.x;
    bool isq = (head < NH);
    const float* src = isq ? (q  + (size_t)s * NH * HD + head * HD)
                           : (kt + (size_t)s * NKV * HD + (head - NH) * HD);
    float x  = src[d];
    float xp = src[(d < 64) ? d + 64 : d - 64];
    int i2 = d & 63;
    float invf = (float)exp(-log(10000.0) * ((double)(2 * i2) / 128.0));
    float ang = (float)(HISTLEN + s) * invf;
    float c  = __half2float(__float2half((float)cos((double)ang)));
    float sn = __half2float(__float2half((float)sin((double)ang)));
    float r = (d < 64) ? (x * c - xp * sn) : (x * c + xp * sn);

    float ss = r * r;
#pragma unroll
    for (int o = 16; o > 0; o >>= 1) ss += __shfl_xor_sync(0xffffffffu, ss, o);
    __shared__ float wsum[4];
    __shared__ float so[128];
    if ((d & 31) == 0) wsum[d >> 5] = ss;
    __syncthreads();
    float tot = wsum[0] + wsum[1] + wsum[2] + wsum[3];
    float inv = rsqrtf(tot * (1.0f / 128.0f) + 1e-6f);
    float w = isq ? qn_w[d] : kn_w[d];
    float out = w * r * inv;
    so[d] = out;
    __syncthreads();
    if (isq) {
        if (d < 64) {
            uint32_t lo_;
            uint32_t hi_ = pack_split(so[2*d], so[2*d + 1], lo_);
            size_t o = (size_t)s * 1024 + head * 64 + d;
            qh[o] = hi_; ql[o] = lo_;
        }
    } else {
        int kvh = head - NH;
        kout[(size_t)kvh * HD * TTOT + (size_t)d * TTOT + HISTLEN + s] = out;
    }
}

// ---------------- masked softmax -> split P ----------------
__global__ void att_softmax_kernel(const float* __restrict__ P,
                                   unsigned* __restrict__ Ph, unsigned* __restrict__ Pl)
{
    int s = blockIdx.x;
    int h = blockIdx.y;
    const float* row = P + ((size_t)h * SQ + s) * HISTLEN;
    int n = s + 1;
    int tid = threadIdx.x;
    __shared__ float red[8];

    float mx = -1e30f;
    for (int t = tid; t < n; t += 256) mx = fmaxf(mx, row[t]);
#pragma unroll
    for (int o = 16; o > 0; o >>= 1) mx = fmaxf(mx, __shfl_xor_sync(0xffffffffu, mx, o));
    if ((tid & 31) == 0) red[tid >> 5] = mx;
    __syncthreads();
    mx = fmaxf(fmaxf(fmaxf(red[0], red[1]), fmaxf(red[2], red[3])),
               fmaxf(fmaxf(red[4], red[5]), fmaxf(red[6], red[7])));

    float sum = 0.f;
    for (int t = tid; t < n; t += 256) sum += __expf(row[t] - mx);
#pragma unroll
    for (int o = 16; o > 0; o >>= 1) sum += __shfl_xor_sync(0xffffffffu, sum, o);
    __syncthreads();
    if ((tid & 31) == 0) red[tid >> 5] = sum;
    __syncthreads();
    sum = red[0] + red[1] + red[2] + red[3] + red[4] + red[5] + red[6] + red[7];
    float inv = 1.f / sum;

    unsigned* oh = Ph + ((size_t)h * SQ + s) * 512;
    unsigned* ol = Pl + ((size_t)h * SQ + s) * 512;
    for (int t2 = tid; t2 < 512; t2 += 256) {
        float p0 = (2*t2     < n) ? __expf(row[2*t2]     - mx) * inv : 0.f;
        float p1 = (2*t2 + 1 < n) ? __expf(row[2*t2 + 1] - mx) * inv : 0.f;
        uint32_t lo_;
        uint32_t hi_ = pack_split(p0, p1, lo_);
        oh[t2] = hi_; ol[t2] = lo_;
    }
}

// ---------------- cache assembly ----------------
__global__ void copy_khist_kernel(const float* __restrict__ src, float* __restrict__ dst)
{
    int idx = blockIdx.x * blockDim.x + threadIdx.x;
    if (idx >= NKV * HD * HISTLEN) return;
    int t = idx & (HISTLEN - 1);
    int row = idx >> 10;
    dst[(size_t)row * TTOT + t] = src[idx];
}

__global__ void copy_vhist_kernel(const float* __restrict__ src, float* __restrict__ dst)
{
    int idx = blockIdx.x * blockDim.x + threadIdx.x;
    if (idx >= NKV * HISTLEN * HD) return;
    int within = idx & (HISTLEN * HD - 1);
    int kv = idx >> 17;
    dst[(size_t)kv * TTOT * HD + within] = src[idx];
}

__global__ void vscatter_kernel(const float* __restrict__ vt, float* __restrict__ dst)
{
    int idx = blockIdx.x * blockDim.x + threadIdx.x;
    if (idx >= SQ * NKV * HD) return;
    int d = idx & 127;
    int kv = (idx >> 7) & 7;
    int s = idx >> 10;
    dst[(size_t)kv * TTOT * HD + (size_t)(HISTLEN + s) * HD + d] = vt[idx];
}

// ---------------- silu(gate)*up -> split pairs ----------------
__global__ void silu_mul_split_kernel(const float* __restrict__ g, const float* __restrict__ u,
                                      unsigned* __restrict__ oh, unsigned* __restrict__ ol, int n2)
{
    int i = blockIdx.x * blockDim.x + threadIdx.x;
    if (i < n2) {
        float x0 = g[2*i],     x1 = g[2*i + 1];
        float a = (x0 / (1.f + expf(-x0))) * u[2*i];
        float b = (x1 / (1.f + expf(-x1))) * u[2*i + 1];
        uint32_t lo_;
        uint32_t hi_ = pack_split(a, b, lo_);
        oh[i] = hi_; ol[i] = lo_;
    }
}

// ---------------- lm head GEMV ----------------
__global__ void lmhead_kernel(const float* __restrict__ x, const float* __restrict__ W,
                              float* __restrict__ out)
{
    __shared__ float xs[256];
    int v = blockIdx.x * 256 + threadIdx.x;
    float acc = 0.f;
    for (int k0 = 0; k0 < DMODEL; k0 += 256) {
        xs[threadIdx.x] = x[k0 + threadIdx.x];
        __syncthreads();
#pragma unroll 16
        for (int k = 0; k < 256; k++)
            acc += xs[k] * W[(size_t)(k0 + k) * VOC + v];
        __syncthreads();
    }
    if (v < VOC) out[v] = acc;
}

// ---------------- host launcher ----------------
extern "C" void kernel_launch(void* const* d_in, const int* in_sizes, int n_in,
                              void* d_out, int out_size)
{
    int IX[19];
    for (int i = 0; i < 19; i++) IX[i] = i;
    if (n_in >= 19 && in_sizes[0] != 1024) {
        const int amap[19] = {5, 6, 17, 1, 2, 3, 9, 14, 7, 18, 15, 8, 13, 10, 4, 16, 0, 12, 11};
        for (int i = 0; i < 19; i++) IX[i] = amap[i];
    }

    const void*  input_ids   = d_in[IX[0]];
    const float* k_cache     = (const float*)d_in[IX[1]];
    const float* v_cache     = (const float*)d_in[IX[2]];
    const void*  embed_q     = d_in[IX[3]];
    const float* embed_scale = (const float*)d_in[IX[4]];
    const float* embed_zp    = (const float*)d_in[IX[5]];
    const float* ln1_w       = (const float*)d_in[IX[6]];
    const float* q_w         = (const float*)d_in[IX[7]];
    const float* k_w         = (const float*)d_in[IX[8]];
    const float* v_w         = (const float*)d_in[IX[9]];
    const float* qn_w        = (const float*)d_in[IX[10]];
    const float* kn_w        = (const float*)d_in[IX[11]];
    const float* o_w         = (const float*)d_in[IX[12]];
    const float* ln2_w       = (const float*)d_in[IX[13]];
    const float* gate_w      = (const float*)d_in[IX[14]];
    const float* up_w        = (const float*)d_in[IX[15]];
    const float* down_w      = (const float*)d_in[IX[16]];
    const float* norm_w      = (const float*)d_in[IX[17]];
    const float* lm_head_w   = (const float*)d_in[IX[18]];
    float* out = (float*)d_out;

    bool write_caches = (out_size >= (int)(VOC + 8u * KVDT));

    float *h_, *q_, *kt_, *vt_, *gate_, *up_, *last_, *att_;
    cudaGetSymbolAddress((void**)&h_,    g_h);
    cudaGetSymbolAddress((void**)&q_,    g_q);
    cudaGetSymbolAddress((void**)&kt_,   g_kt);
    cudaGetSymbolAddress((void**)&vt_,   g_vt);
    cudaGetSymbolAddress((void**)&gate_, g_gate);
    cudaGetSymbolAddress((void**)&up_,   g_up);
    cudaGetSymbolAddress((void**)&last_, g_last);
    cudaGetSymbolAddress((void**)&att_,  g_att);

    unsigned *wqh,*wql,*wkh,*wkl,*wvh,*wvl,*woh,*wol,*wgh,*wgl,*wuh,*wul,*wdh,*wdl;
    unsigned *kth,*ktl,*vth,*vtl,*hnh,*hnl,*qh,*ql,*Ph,*Pl,*ctxh,*ctxl,*guh,*gul;
    cudaGetSymbolAddress((void**)&wqh, g_wqh); cudaGetSymbolAddress((void**)&wql, g_wql);
    cudaGetSymbolAddress((void**)&wkh, g_wkh); cudaGetSymbolAddress((void**)&wkl, g_wkl);
    cudaGetSymbolAddress((void**)&wvh, g_wvh); cudaGetSymbolAddress((void**)&wvl, g_wvl);
    cudaGetSymbolAddress((void**)&woh, g_woh); cudaGetSymbolAddress((void**)&wol, g_wol);
    cudaGetSymbolAddress((void**)&wgh, g_wgh); cudaGetSymbolAddress((void**)&wgl, g_wgl);
    cudaGetSymbolAddress((void**)&wuh, g_wuh); cudaGetSymbolAddress((void**)&wul, g_wul);
    cudaGetSymbolAddress((void**)&wdh, g_wdh); cudaGetSymbolAddress((void**)&wdl, g_wdl);
    cudaGetSymbolAddress((void**)&kth, g_kth); cudaGetSymbolAddress((void**)&ktl, g_ktl);
    cudaGetSymbolAddress((void**)&vth, g_vth); cudaGetSymbolAddress((void**)&vtl, g_vtl);
    cudaGetSymbolAddress((void**)&hnh, g_hnh); cudaGetSymbolAddress((void**)&hnl, g_hnl);
    cudaGetSymbolAddress((void**)&qh,  g_qh);  cudaGetSymbolAddress((void**)&ql,  g_ql);
    cudaGetSymbolAddress((void**)&Ph,  g_Ph);  cudaGetSymbolAddress((void**)&Pl,  g_Pl);
    cudaGetSymbolAddress((void**)&ctxh,g_ctxh);cudaGetSymbolAddress((void**)&ctxl,g_ctxl);
    cudaGetSymbolAddress((void**)&guh, g_guh); cudaGetSymbolAddress((void**)&gul, g_gul);

    sniff_kernel<<<1, 1>>>(input_ids, embed_q);
    embed_kernel<<<(SQ*DMODEL + 255) / 256, 256>>>(input_ids, embed_q, embed_scale, embed_zp, h_);

    // ---- pre-split all weights ([K][N] -> [N][K/2] hi/lo) ----
    wsplit_kernel<<<dim3((NH*HD)/32,  DMODEL/64, NL), 256>>>(q_w,  wqh, wql, DMODEL, NH*HD,
        (long long)DMODEL*NH*HD,  (long long)(NH*HD)*(DMODEL/2));
    wsplit_kernel<<<dim3((NKV*HD)/32, DMODEL/64, NL), 256>>>(k_w,  wkh, wkl, DMODEL, NKV*HD,
        (long long)DMODEL*NKV*HD, (long long)(NKV*HD)*(DMODEL/2));
    wsplit_kernel<<<dim3((NKV*HD)/32, DMODEL/64, NL), 256>>>(v_w,  wvh, wvl, DMODEL, NKV*HD,
        (long long)DMODEL*NKV*HD, (long long)(NKV*HD)*(DMODEL/2));
    wsplit_kernel<<<dim3(DMODEL/32, (NH*HD)/64, NL), 256>>>(o_w,  woh, wol, NH*HD, DMODEL,
        (long long)(NH*HD)*DMODEL, (long long)DMODEL*(NH*HD/2));
    wsplit_kernel<<<dim3(FFD/32, DMODEL/64, NL), 256>>>(gate_w, wgh, wgl, DMODEL, FFD,
        (long long)DMODEL*FFD, (long long)FFD*(DMODEL/2));
    wsplit_kernel<<<dim3(FFD/32, DMODEL/64, NL), 256>>>(up_w,   wuh, wul, DMODEL, FFD,
        (long long)DMODEL*FFD, (long long)FFD*(DMODEL/2));
    wsplit_kernel<<<dim3(DMODEL/32, FFD/64, NL), 256>>>(down_w, wdh, wdl, FFD, DMODEL,
        (long long)FFD*DMODEL, (long long)DMODEL*(FFD/2));
    // caches: k [d][t] -> [t][d/2]; v [t][d] -> [d][t/2]  (z = L*KV)
    wsplit_kernel<<<dim3(HISTLEN/32, HD/64, NL*NKV), 256>>>(k_cache, kth, ktl, HD, HISTLEN,
        (long long)HD*HISTLEN, 65536LL);
    wsplit_kernel<<<dim3(HD/32, HISTLEN/64, NL*NKV), 256>>>(v_cache, vth, vtl, HISTLEN, HD,
        (long long)HISTLEN*HD, 65536LL);

    for (int l = 0; l < NL; l++) {
        float* kout = out + VOC + (size_t)l * KVDT;
        float* vout = out + VOC + (size_t)(NL + l) * KVDT;
        if (!write_caches) { kout = att_; vout = att_ + KVDT; }
        const float* kcl = k_cache + (size_t)l * NKV * HD * HISTLEN;
        const float* vcl = v_cache + (size_t)l * NKV * HISTLEN * HD;

        if (write_caches) {
            copy_khist_kernel<<<(NKV*HD*HISTLEN + 255) / 256, 256>>>(kcl, kout);
            copy_vhist_kernel<<<(NKV*HISTLEN*HD + 255) / 256, 256>>>(vcl, vout);
        }

        rmsnorm_split_kernel<<<SQ, 256>>>(h_, ln1_w + (size_t)l * DMODEL, hnh, hnl, DMODEL);

        // QKV  (A = hn split, B = weight split)
        gemm_sp<<<dim3((NH*HD)/128, SQ/128, 1), 256>>>(hnh, hnl,
            wqh + (size_t)l*2048*1024, wql + (size_t)l*2048*1024,
            q_, 0, 0, NH*HD, 1024, 1024, 1024, NH*HD, 0, 0, 0, 0, 0);
        gemm_sp<<<dim3((NKV*HD)/128, SQ/128, 1), 256>>>(hnh, hnl,
            wkh + (size_t)l*1024*1024, wkl + (size_t)l*1024*1024,
            kt_, 0, 0, NKV*HD, 1024, 1024, 1024, NKV*HD, 0, 0, 0, 0, 0);
        gemm_sp<<<dim3((NKV*HD)/128, SQ/128, 1), 256>>>(hnh, hnl,
            wvh + (size_t)l*1024*1024, wvl + (size_t)l*1024*1024,
            vt_, 0, 0, NKV*HD, 1024, 1024, 1024, NKV*HD, 0, 0, 0, 0, 0);

        rope_norm_kernel<<<dim3(SQ, NH + NKV), 128>>>(q_, kt_,
            qn_w + (size_t)l * HD, kn_w + (size_t)l * HD, kout, qh, ql);
        if (write_caches)
            vscatter_kernel<<<(SQ*NKV*HD + 255) / 256, 256>>>(vt_, vout);

        // scores: A = q split (per head), B = kT split (per kv head)
        gemm_sp<<<dim3(HISTLEN/128, SQ/128, NH), 256>>>(qh, ql,
            kth + (size_t)l*NKV*65536, ktl + (size_t)l*NKV*65536,
            att_, 0, 0, HISTLEN, 64, 1024, 64, HISTLEN,
            64LL, 65536LL, (long long)SQ*HISTLEN, 1, 0);

        att_softmax_kernel<<<dim3(SQ, NH), 256>>>(att_, Ph, Pl);

        // ctx: A = P split, B = vT split -> split-out to ctx arrays
        gemm_sp<<<dim3(HD/128, SQ/128, NH), 256>>>(Ph, Pl,
            vth + (size_t)l*NKV*65536, vtl + (size_t)l*NKV*65536,
            0, ctxh, ctxl, HD, 512, 512, 512, 1024,
            (long long)SQ*512, 65536LL, 64LL, 1, 2);

        // O projection (residual accumulate into h)
        gemm_sp<<<dim3(DMODEL/128, SQ/128, 1), 256>>>(ctxh, ctxl,
            woh + (size_t)l*2048*1024, wol + (size_t)l*2048*1024,
            h_, 0, 0, DMODEL, 1024, 1024, 1024, DMODEL, 0, 0, 0, 0, 1);

        rmsnorm_split_kernel<<<SQ, 256>>>(h_, ln2_w + (size_t)l * DMODEL, hnh, hnl, DMODEL);

        gemm_sp<<<dim3(FFD/128, SQ/128, 1), 256>>>(hnh, hnl,
            wgh + (size_t)l*8192*1024, wgl + (size_t)l*8192*1024,
            gate_, 0, 0, FFD, 1024, 1024, 1024, FFD, 0, 0, 0, 0, 0);
        gemm_sp<<<dim3(FFD/128, SQ/128, 1), 256>>>(hnh, hnl,
            wuh + (size_t)l*8192*1024, wul + (size_t)l*8192*1024,
            up_, 0, 0, FFD, 1024, 1024, 1024, FFD, 0, 0, 0, 0, 0);
        silu_mul_split_kernel<<<(SQ*FFD/2 + 255) / 256, 256>>>(gate_, up_, guh, gul, SQ*FFD/2);
        gemm_sp<<<dim3(DMODEL/128, SQ/128, 1), 256>>>(guh, gul,
            wdh + (size_t)l*2048*4096, wdl + (size_t)l*2048*4096,
            h_, 0, 0, DMODEL, 4096, 4096, 4096, DMODEL, 0, 0, 0, 0, 1);
    }

    rmsnorm_kernel<<<1, 256>>>(h_ + (size_t)(SQ - 1) * DMODEL, norm_w, last_, DMODEL);
    lmhead_kernel<<<VOC / 256, 256>>>(last_, lm_head_w, out);
}